// round 1
// baseline (speedup 1.0000x reference)
#include <cuda_runtime.h>
#include <math.h>

// ---------------------------------------------------------------------------
// Problem constants
//   B=8, L=2048, D=1024, K=32, J=512
//   backbone0 seq n0 = 2050, summarize seq ns = 514, backbone1 seq n1 = 2082
//   Pad sequences to NP=2176 (17*128) and NS=640 (5*128) so every GEMM dim is
//   a multiple of the tile sizes -> zero bounds checks, full float4 loads.
//   Softmax masks key positions >= n to 0, so padded K/V rows cannot leak.
// ---------------------------------------------------------------------------
#define Bn 8
#define Dn 1024
#define NP 2176
#define NS 640

// Scratch (static device globals; no runtime allocation)
__device__ float g_X[(size_t)Bn * NP * Dn];
__device__ float g_Q[(size_t)Bn * NP * Dn];
__device__ float g_K[(size_t)Bn * NP * Dn];
__device__ float g_V[(size_t)Bn * NP * Dn];
__device__ float g_O[(size_t)Bn * NP * Dn];
__device__ float g_H[(size_t)Bn * NP * Dn];
__device__ float g_S[(size_t)Bn * NP * NP];
__device__ float g_M1[128 * Dn];
__device__ float g_S1[128 * Dn];
__device__ float g_Qn[128 * Dn];
__device__ float g_Kp[128 * Dn];
__device__ float g_P1[Bn * Dn];

// ---------------------------------------------------------------------------
// SGEMM: C = scale * A * op(B) [+ bias broadcast over rows]
//   A: M x K row-major (lda = K)
//   B: NN -> K x N row-major (ldb = N); NT -> N x K row-major (ldb = K)
//   C: M x N row-major (ldc = N)
//   All of M, N multiples of 128; K multiple of 8. Batched via blockIdx.z.
// ---------------------------------------------------------------------------
template <bool TRANSB, bool BIAS>
__global__ void __launch_bounds__(256)
sgemm(const float* __restrict__ A, const float* __restrict__ Bm,
      float* __restrict__ C, const float* __restrict__ bias,
      int N, int Kd, float scale,
      long long sA, long long sB, long long sC)
{
    A  += (long long)blockIdx.z * sA;
    Bm += (long long)blockIdx.z * sB;
    C  += (long long)blockIdx.z * sC;

    __shared__ float As[8][128];
    __shared__ float Bs[8][128];

    const int t  = threadIdx.x;
    const int tx = t & 15;
    const int ty = t >> 4;
    const int row0 = blockIdx.y * 128;
    const int col0 = blockIdx.x * 128;

    const int aRow = t >> 1;          // 0..127
    const int aCol = (t & 1) << 2;    // 0 or 4
    const int bRow = t >> 5;          // 0..7
    const int bCol = (t & 31) << 2;   // 0..124

    float acc[8][8];
#pragma unroll
    for (int i = 0; i < 8; i++)
#pragma unroll
        for (int j = 0; j < 8; j++) acc[i][j] = 0.f;

    const float* Aptr = A + (long long)(row0 + aRow) * Kd + aCol;
    const float* Bptr = TRANSB ? (Bm + (long long)(col0 + aRow) * Kd + aCol)
                               : (Bm + (long long)bRow * N + col0 + bCol);

    for (int k0 = 0; k0 < Kd; k0 += 8) {
        float4 av = *(const float4*)(Aptr + k0);
        As[aCol + 0][aRow] = av.x;
        As[aCol + 1][aRow] = av.y;
        As[aCol + 2][aRow] = av.z;
        As[aCol + 3][aRow] = av.w;
        if (TRANSB) {
            float4 bv = *(const float4*)(Bptr + k0);
            Bs[aCol + 0][aRow] = bv.x;
            Bs[aCol + 1][aRow] = bv.y;
            Bs[aCol + 2][aRow] = bv.z;
            Bs[aCol + 3][aRow] = bv.w;
        } else {
            float4 bv = *(const float4*)(Bptr + (long long)k0 * N);
            *(float4*)&Bs[bRow][bCol] = bv;
        }
        __syncthreads();
#pragma unroll
        for (int kk = 0; kk < 8; kk++) {
            float ar[8], br[8];
            *(float4*)&ar[0] = *(const float4*)&As[kk][ty * 8];
            *(float4*)&ar[4] = *(const float4*)&As[kk][ty * 8 + 4];
            *(float4*)&br[0] = *(const float4*)&Bs[kk][tx * 8];
            *(float4*)&br[4] = *(const float4*)&Bs[kk][tx * 8 + 4];
#pragma unroll
            for (int i = 0; i < 8; i++)
#pragma unroll
                for (int j = 0; j < 8; j++)
                    acc[i][j] = fmaf(ar[i], br[j], acc[i][j]);
        }
        __syncthreads();
    }

#pragma unroll
    for (int i = 0; i < 8; i++) {
        long long r = row0 + ty * 8 + i;
#pragma unroll
        for (int j = 0; j < 8; j += 4) {
            int c = col0 + tx * 8 + j;
            float4 v;
            v.x = acc[i][j + 0] * scale;
            v.y = acc[i][j + 1] * scale;
            v.z = acc[i][j + 2] * scale;
            v.w = acc[i][j + 3] * scale;
            if (BIAS) {
                v.x += bias[c + 0];
                v.y += bias[c + 1];
                v.z += bias[c + 2];
                v.w += bias[c + 3];
            }
            *(float4*)(C + r * N + c) = v;
        }
    }
}

// ---------------------------------------------------------------------------
// Row softmax over scores S[b][row][0..n) with row stride npad.
// Columns [n, npad) are zeroed so padded keys contribute nothing to P@V.
// Grid: (n, B); block: 256.
// ---------------------------------------------------------------------------
__global__ void softmax_rows(float* __restrict__ S, int n, int npad)
{
    float* row = S + ((long long)blockIdx.y * npad + blockIdx.x) * npad;
    const int t = threadIdx.x;
    __shared__ float red[256];

    float m = -1e30f;
    for (int j = t; j < n; j += 256) m = fmaxf(m, row[j]);
    red[t] = m;
    __syncthreads();
    for (int s = 128; s > 0; s >>= 1) {
        if (t < s) red[t] = fmaxf(red[t], red[t + s]);
        __syncthreads();
    }
    m = red[0];
    __syncthreads();

    float sum = 0.f;
    for (int j = t; j < n; j += 256) {
        float e = __expf(row[j] - m);
        row[j] = e;
        sum += e;
    }
    red[t] = sum;
    __syncthreads();
    for (int s = 128; s > 0; s >>= 1) {
        if (t < s) red[t] += red[t + s];
        __syncthreads();
    }
    float inv = 1.f / red[0];

    for (int j = t; j < n; j += 256) row[j] *= inv;
    for (int j = n + t; j < npad; j += 256) row[j] = 0.f;
}

// ---------------------------------------------------------------------------
// Input assembly kernels
// ---------------------------------------------------------------------------
// input_h0 = [P0(zeros), seg0 (2048), P0] padded to NP
__global__ void build_x0(const float* __restrict__ seg0, float* __restrict__ X)
{
    int b = blockIdx.y;
    long long i = (long long)blockIdx.x * 256 + threadIdx.x;
    int pos = (int)(i >> 10);
    int d = (int)(i & 1023);
    float v = 0.f;
    if (pos >= 1 && pos <= 2048)
        v = seg0[((long long)b * 2048 + (pos - 1)) * 1024 + d];
    X[(long long)b * NP * 1024 + i] = v;
}

// summarize input = [T, seg1[:512], T] padded to NS
__global__ void build_xs(const float* __restrict__ seg1,
                         const float* __restrict__ pe, float* __restrict__ X)
{
    int b = blockIdx.y;
    long long i = (long long)blockIdx.x * 256 + threadIdx.x;
    int pos = (int)(i >> 10);
    int d = (int)(i & 1023);
    float v = 0.f;
    if (pos == 0 || pos == 513) v = pe[d];
    else if (pos >= 1 && pos <= 512)
        v = seg1[((long long)b * 2048 + (pos - 1)) * 1024 + d];
    X[(long long)b * NS * 1024 + i] = v;
}

// input_h1 = [seg0[-32:], P1, seg1 (2048), P1] padded to NP
__global__ void build_x1(const float* __restrict__ seg0,
                         const float* __restrict__ seg1,
                         const float* __restrict__ P1, float* __restrict__ X)
{
    int b = blockIdx.y;
    long long i = (long long)blockIdx.x * 256 + threadIdx.x;
    int pos = (int)(i >> 10);
    int d = (int)(i & 1023);
    float v = 0.f;
    if (pos < 32)
        v = seg0[((long long)b * 2048 + (2016 + pos)) * 1024 + d];
    else if (pos == 32 || pos == 2081)
        v = P1[b * 1024 + d];
    else if (pos >= 33 && pos <= 2080)
        v = seg1[((long long)b * 2048 + (pos - 33)) * 1024 + d];
    X[(long long)b * NP * 1024 + i] = v;
}

// copy tokens [33, 33+tokens) of H (stride npad) into output region
__global__ void copy_out(const float* __restrict__ H, float* __restrict__ out,
                         int tokens, int npad, long long off)
{
    int b = blockIdx.y;
    long long i = (long long)blockIdx.x * 256 + threadIdx.x;
    out[off + (long long)b * tokens * 1024 + i] =
        H[(long long)b * npad * 1024 + (long long)33 * 1024 + i];
}

// extract token `token` for all 8 batches into a 128x1024 buffer (rows 8..127 = 0)
__global__ void copy_pad128(const float* __restrict__ H, float* __restrict__ dst,
                            int npad, int token)
{
    long long i = (long long)blockIdx.x * 256 + threadIdx.x;
    int r = (int)(i >> 10);
    int d = (int)(i & 1023);
    dst[i] = (r < Bn) ? H[((long long)r * npad + token) * 1024 + d] : 0.f;
}

// Tiny 8-way memory attention: P1[b] = softmax_j(Qn[b].Kp[j]/32) @ M1
__global__ void mem_attn(const float* __restrict__ Qn, const float* __restrict__ Kp,
                         const float* __restrict__ M1, float* __restrict__ P1)
{
    int b = blockIdx.x;
    int t = threadIdx.x;
    __shared__ float red[256];
    __shared__ float attn[Bn];

    for (int j = 0; j < Bn; j++) {
        float p = 0.f;
        for (int d = t; d < 1024; d += 256)
            p += Qn[b * 1024 + d] * Kp[j * 1024 + d];
        red[t] = p;
        __syncthreads();
        for (int s = 128; s > 0; s >>= 1) {
            if (t < s) red[t] += red[t + s];
            __syncthreads();
        }
        if (t == 0) attn[j] = red[0] * 0.03125f;
        __syncthreads();
    }
    if (t == 0) {
        float m = -1e30f;
        for (int j = 0; j < Bn; j++) m = fmaxf(m, attn[j]);
        float s = 0.f;
        for (int j = 0; j < Bn; j++) { attn[j] = __expf(attn[j] - m); s += attn[j]; }
        float inv = 1.f / s;
        for (int j = 0; j < Bn; j++) attn[j] *= inv;
    }
    __syncthreads();
    for (int d = t; d < 1024; d += 256) {
        float v = 0.f;
#pragma unroll
        for (int j = 0; j < Bn; j++) v += attn[j] * M1[j * 1024 + d];
        P1[b * 1024 + d] = v;
    }
}

// ---------------------------------------------------------------------------
// Host-side backbone: X -> H (all pointers are device scratch / weights)
// ---------------------------------------------------------------------------
static void run_backbone(float* pX, float* pQ, float* pK, float* pV,
                         float* pO, float* pH, float* pS,
                         const float* Wq, const float* bq,
                         const float* Wk, const float* bk,
                         const float* Wv, const float* bv,
                         const float* Wo, const float* bo,
                         int n, int npad)
{
    int M = Bn * npad;
    dim3 gProj(Dn / 128, M / 128, 1);
    sgemm<false, true><<<gProj, 256>>>(pX, Wq, pQ, bq, Dn, Dn, 1.f, 0, 0, 0);
    sgemm<false, true><<<gProj, 256>>>(pX, Wk, pK, bk, Dn, Dn, 1.f, 0, 0, 0);
    sgemm<false, true><<<gProj, 256>>>(pX, Wv, pV, bv, Dn, Dn, 1.f, 0, 0, 0);

    dim3 gSc(npad / 128, npad / 128, Bn);
    sgemm<true, false><<<gSc, 256>>>(pQ, pK, pS, nullptr, npad, Dn, 0.03125f,
                                     (long long)npad * Dn, (long long)npad * Dn,
                                     (long long)npad * npad);

    softmax_rows<<<dim3(n, Bn), 256>>>(pS, n, npad);

    dim3 gAV(Dn / 128, npad / 128, Bn);
    sgemm<false, false><<<gAV, 256>>>(pS, pV, pO, nullptr, Dn, npad, 1.f,
                                      (long long)npad * npad, (long long)npad * Dn,
                                      (long long)npad * Dn);

    sgemm<false, true><<<gProj, 256>>>(pO, Wo, pH, bo, Dn, Dn, 1.f, 0, 0, 0);
}

// ---------------------------------------------------------------------------
extern "C" void kernel_launch(void* const* d_in, const int* in_sizes, int n_in,
                              void* d_out, int out_size)
{
    const float* seg0   = (const float*)d_in[0];
    const float* seg1   = (const float*)d_in[1];
    const float* pe     = (const float*)d_in[2];
    const float* Wq_mem = (const float*)d_in[3];
    const float* bq_mem = (const float*)d_in[4];
    const float* Wk_mem = (const float*)d_in[5];
    const float* bk_mem = (const float*)d_in[6];
    const float* Wq     = (const float*)d_in[7];
    const float* bq     = (const float*)d_in[8];
    const float* Wk     = (const float*)d_in[9];
    const float* bk     = (const float*)d_in[10];
    const float* Wv     = (const float*)d_in[11];
    const float* bv     = (const float*)d_in[12];
    const float* Wo     = (const float*)d_in[13];
    const float* bo     = (const float*)d_in[14];
    float* out = (float*)d_out;

    float *pX, *pQ, *pK, *pV, *pO, *pH, *pS, *pM1, *pS1, *pQn, *pKp, *pP1;
    cudaGetSymbolAddress((void**)&pX, g_X);
    cudaGetSymbolAddress((void**)&pQ, g_Q);
    cudaGetSymbolAddress((void**)&pK, g_K);
    cudaGetSymbolAddress((void**)&pV, g_V);
    cudaGetSymbolAddress((void**)&pO, g_O);
    cudaGetSymbolAddress((void**)&pH, g_H);
    cudaGetSymbolAddress((void**)&pS, g_S);
    cudaGetSymbolAddress((void**)&pM1, g_M1);
    cudaGetSymbolAddress((void**)&pS1, g_S1);
    cudaGetSymbolAddress((void**)&pQn, g_Qn);
    cudaGetSymbolAddress((void**)&pKp, g_Kp);
    cudaGetSymbolAddress((void**)&pP1, g_P1);

    // ---- Stage A: backbone over input_h0 (n = 2050) ----
    build_x0<<<dim3(NP * Dn / 256, Bn), 256>>>(seg0, pX);
    run_backbone(pX, pQ, pK, pV, pO, pH, pS,
                 Wq, bq, Wk, bk, Wv, bv, Wo, bo, 2050, NP);
    // out0 = tokens 33..2048 (2016 tokens)
    copy_out<<<dim3(2016 * Dn / 256, Bn), 256>>>(pH, out, 2016, NP, 0LL);
    // M1 = token 2049
    copy_pad128<<<dim3(128 * Dn / 256), 256>>>(pH, pM1, NP, 2049);

    // ---- Stage B: summarize(seg1) (n = 514) ----
    build_xs<<<dim3(NS * Dn / 256, Bn), 256>>>(seg1, pe, pX);
    run_backbone(pX, pQ, pK, pV, pO, pH, pS,
                 Wq, bq, Wk, bk, Wv, bv, Wo, bo, 514, NS);
    // S1 = token 512
    copy_pad128<<<dim3(128 * Dn / 256), 256>>>(pH, pS1, NS, 512);

    // ---- Stage C: memory attention (tiny) ----
    dim3 gMem(Dn / 128, 1, 1);
    sgemm<false, true><<<gMem, 256>>>(pS1, Wq_mem, pQn, bq_mem, Dn, Dn, 1.f, 0, 0, 0);
    sgemm<false, true><<<gMem, 256>>>(pM1, Wk_mem, pKp, bk_mem, Dn, Dn, 1.f, 0, 0, 0);
    mem_attn<<<Bn, 256>>>(pQn, pKp, pM1, pP1);

    // ---- Stage D: backbone over input_h1 (n = 2082) ----
    build_x1<<<dim3(NP * Dn / 256, Bn), 256>>>(seg0, seg1, pP1, pX);
    run_backbone(pX, pQ, pK, pV, pO, pH, pS,
                 Wq, bq, Wk, bk, Wv, bv, Wo, bo, 2082, NP);
    // out1 = tokens 33..2080 (2048 tokens)
    copy_out<<<dim3(2048 * Dn / 256, Bn), 256>>>(pH, out, 2048, NP,
                                                 (long long)Bn * 2016 * Dn);
}

// round 3
// speedup vs baseline: 2.9024x; 2.9024x over previous
#include <cuda_runtime.h>
#include <cuda_bf16.h>
#include <math.h>
#include <cstdint>

// ---------------------------------------------------------------------------
// Problem constants: B=8, L=2048, D=1024, K=32, J=512
//   backbone0 n=2050, summarize n=514, backbone1 n=2082
//   Pad to NP=2176 (17*128) and NS=640 (5*128).
// ---------------------------------------------------------------------------
#define Bn 8
#define Dn 1024
#define NP 2176
#define NS 640

#define EL_XD ((size_t)Bn * NP * Dn)
#define EL_PP ((size_t)Bn * NP * NP)

__device__ __align__(256) __nv_bfloat16 g_Xh[EL_XD], g_Xl[EL_XD];
__device__ __align__(256) __nv_bfloat16 g_Qh[EL_XD], g_Ql[EL_XD];
__device__ __align__(256) __nv_bfloat16 g_Kh[EL_XD], g_Kl[EL_XD];
__device__ __align__(256) __nv_bfloat16 g_Vth[EL_XD], g_Vtl[EL_XD]; // V transposed
__device__ __align__(256) __nv_bfloat16 g_Oh[EL_XD], g_Ol[EL_XD];
__device__ __align__(256) __nv_bfloat16 g_Ph[EL_PP], g_Pl[EL_PP];
__device__ __align__(256) float g_S[EL_PP];
__device__ __align__(256) float g_H[EL_XD];
__device__ __align__(256) __nv_bfloat16 g_WqTh[Dn*Dn], g_WqTl[Dn*Dn];
__device__ __align__(256) __nv_bfloat16 g_WkTh[Dn*Dn], g_WkTl[Dn*Dn];
__device__ __align__(256) __nv_bfloat16 g_WvTh[Dn*Dn], g_WvTl[Dn*Dn];
__device__ __align__(256) __nv_bfloat16 g_WoTh[Dn*Dn], g_WoTl[Dn*Dn];
__device__ __align__(256) float g_M1[128 * Dn];
__device__ __align__(256) float g_S1[128 * Dn];
__device__ __align__(256) float g_Qn[128 * Dn];
__device__ __align__(256) float g_Kp[128 * Dn];
__device__ __align__(256) float g_P1[Bn * Dn];

// ---------------------------------------------------------------------------
// helpers
// ---------------------------------------------------------------------------
__device__ __forceinline__ uint32_t smem_u32(const void* p) {
    uint32_t a;
    asm("{ .reg .u64 t; cvta.to.shared.u64 t, %1; cvt.u32.u64 %0, t; }"
        : "=r"(a) : "l"(p));
    return a;
}
__device__ __forceinline__ void split2(float v, __nv_bfloat16& h, __nv_bfloat16& l) {
    h = __float2bfloat16_rn(v);
    l = __float2bfloat16_rn(v - __bfloat162float(h));
}
// SW128 swizzle for [row][64 bf16] tiles (128B rows): 16B-chunk col XOR row%8
__device__ __forceinline__ uint32_t swz(int row, int col16) {
    return ((uint32_t)row << 7) | ((uint32_t)((col16 ^ row) & 7) << 4);
}
__device__ __forceinline__ void ldsm4(uint32_t* r, uint32_t addr) {
    asm volatile("ldmatrix.sync.aligned.m8n8.x4.shared.b16 {%0,%1,%2,%3}, [%4];"
        : "=r"(r[0]), "=r"(r[1]), "=r"(r[2]), "=r"(r[3]) : "r"(addr));
}
__device__ __forceinline__ void mma_bf16(float* d, const uint32_t* a, const uint32_t* b) {
    asm volatile(
        "mma.sync.aligned.m16n8k16.row.col.f32.bf16.bf16.f32 "
        "{%0,%1,%2,%3}, {%4,%5,%6,%7}, {%8,%9}, {%0,%1,%2,%3};"
        : "+f"(d[0]), "+f"(d[1]), "+f"(d[2]), "+f"(d[3])
        : "r"(a[0]), "r"(a[1]), "r"(a[2]), "r"(a[3]), "r"(b[0]), "r"(b[1]));
}

// ---------------------------------------------------------------------------
// split-bf16 tensor-core GEMM: C = scale*(Ah+Al)*(Bh+Bl)^T (+bias over cols)
//   A: [M][Kd] K-major split bf16; B: [N][Kd] K-major split bf16.
//   CTA tile 128x128, warp tile 64x32 (8 warps 2x4), K-chunk 64,
//   double-buffered cp.async, SW128 smem + ldmatrix, fp32 accum.
//   MODE 0: fp32 out; MODE 1: split bf16 out; MODE 2: split bf16 TRANSPOSED.
//   Batched via blockIdx.z (element strides sA, sB, sC).
// ---------------------------------------------------------------------------
#define TG_SMEM (2 * 4 * 16384)  // 131072 bytes

__device__ __forceinline__ void fill_chunk(uint32_t sm,
    const __nv_bfloat16* Ah, const __nv_bfloat16* Al,
    const __nv_bfloat16* Bh, const __nv_bfloat16* Bl,
    int Kd, int t, int c)
{
    long long k0 = (long long)c << 6;
#pragma unroll
    for (int i = 0; i < 4; i++) {
        int seg = t + (i << 8);          // 0..1023 = row*8 + chunk
        int row = seg >> 3;
        int sc  = seg & 7;
        uint32_t so = swz(row, sc);
        long long go = (long long)row * Kd + k0 + ((long long)sc << 3);
        asm volatile("cp.async.cg.shared.global [%0], [%1], 16;"
                     :: "r"(sm + so), "l"(Ah + go));
        asm volatile("cp.async.cg.shared.global [%0], [%1], 16;"
                     :: "r"(sm + 16384u + so), "l"(Al + go));
        asm volatile("cp.async.cg.shared.global [%0], [%1], 16;"
                     :: "r"(sm + 32768u + so), "l"(Bh + go));
        asm volatile("cp.async.cg.shared.global [%0], [%1], 16;"
                     :: "r"(sm + 49152u + so), "l"(Bl + go));
    }
}

template <int MODE, bool BIAS>
__global__ void __launch_bounds__(256, 1)
tgemm(const __nv_bfloat16* __restrict__ Ah, const __nv_bfloat16* __restrict__ Al,
      const __nv_bfloat16* __restrict__ Bh, const __nv_bfloat16* __restrict__ Bl,
      float* __restrict__ Cf, __nv_bfloat16* __restrict__ Ch,
      __nv_bfloat16* __restrict__ Cl, const float* __restrict__ bias,
      int Kd, int ldc, float scale,
      long long sA, long long sB, long long sC)
{
    extern __shared__ __align__(1024) char smem[];
    const int tid = threadIdx.x, wid = tid >> 5, lane = tid & 31;
    const long long z = blockIdx.z;
    Ah += z * sA; Al += z * sA; Bh += z * sB; Bl += z * sB;
    if (MODE == 0) Cf += z * sC; else { Ch += z * sC; Cl += z * sC; }

    const uint32_t sb = smem_u32(smem);
    const __nv_bfloat16* At_h = Ah + (long long)blockIdx.y * 128 * Kd;
    const __nv_bfloat16* At_l = Al + (long long)blockIdx.y * 128 * Kd;
    const __nv_bfloat16* Bt_h = Bh + (long long)blockIdx.x * 128 * Kd;
    const __nv_bfloat16* Bt_l = Bl + (long long)blockIdx.x * 128 * Kd;

    const int wr = wid >> 2, wc = wid & 3;    // 2 x 4 warp grid
    const int m0 = wr * 64, n0 = wc * 32;

    float acc[4][4][4];
#pragma unroll
    for (int i = 0; i < 4; i++)
#pragma unroll
        for (int j = 0; j < 4; j++)
#pragma unroll
            for (int r = 0; r < 4; r++) acc[i][j][r] = 0.f;

    const int NC = Kd >> 6;
    fill_chunk(sb, At_h, At_l, Bt_h, Bt_l, Kd, tid, 0);
    asm volatile("cp.async.commit_group;");

#pragma unroll 1
    for (int c = 0; c < NC; c++) {
        if (c + 1 < NC) {
            fill_chunk(sb + (uint32_t)((c + 1) & 1) * 65536u,
                       At_h, At_l, Bt_h, Bt_l, Kd, tid, c + 1);
            asm volatile("cp.async.commit_group;");
            asm volatile("cp.async.wait_group 1;");
        } else {
            asm volatile("cp.async.wait_group 0;");
        }
        __syncthreads();

        const uint32_t tb  = sb + (uint32_t)(c & 1) * 65536u;
        const uint32_t aAh = tb, aAl = tb + 16384u;
        const uint32_t aBh = tb + 32768u, aBl = tb + 49152u;

#pragma unroll
        for (int kk = 0; kk < 4; kk++) {
            const int k16 = kk << 1;  // col16 base
            uint32_t Ahf[4][4], Alf[4][4], Bhf[2][4], Blf[2][4];
            const int ar = m0 + (lane & 15);
            const int ac = k16 + (lane >> 4);
#pragma unroll
            for (int i = 0; i < 4; i++) {
                const uint32_t off = swz(ar + 16 * i, ac);
                ldsm4(Ahf[i], aAh + off);
                ldsm4(Alf[i], aAl + off);
            }
            const int br = n0 + ((lane >> 4) << 3) + (lane & 7);
            const int bc = k16 + ((lane >> 3) & 1);
#pragma unroll
            for (int j2 = 0; j2 < 2; j2++) {
                const uint32_t off = swz(br + 16 * j2, bc);
                ldsm4(Bhf[j2], aBh + off);
                ldsm4(Blf[j2], aBl + off);
            }
#pragma unroll
            for (int i = 0; i < 4; i++)
#pragma unroll
                for (int jt = 0; jt < 4; jt++) {
                    const uint32_t* bh = &Bhf[jt >> 1][(jt & 1) << 1];
                    const uint32_t* bl = &Blf[jt >> 1][(jt & 1) << 1];
                    mma_bf16(acc[i][jt], Ahf[i], bh);
                    mma_bf16(acc[i][jt], Alf[i], bh);
                    mma_bf16(acc[i][jt], Ahf[i], bl);
                }
        }
        __syncthreads();
    }

    // ---------------- epilogue ----------------
    const int row0 = blockIdx.y * 128, col0 = blockIdx.x * 128;
    const int rl = lane >> 2;              // 0..7
    const int cl = (lane & 3) << 1;        // 0,2,4,6
#pragma unroll
    for (int i = 0; i < 4; i++) {
        const long long rg0 = row0 + m0 + i * 16 + rl;
        const long long rg1 = rg0 + 8;
#pragma unroll
        for (int j = 0; j < 4; j++) {
            const int cg = col0 + n0 + j * 8 + cl;
            float v00 = acc[i][j][0] * scale, v01 = acc[i][j][1] * scale;
            float v10 = acc[i][j][2] * scale, v11 = acc[i][j][3] * scale;
            if (BIAS) {
                const float b0 = bias[cg], b1 = bias[cg + 1];
                v00 += b0; v01 += b1; v10 += b0; v11 += b1;
            }
            if (MODE == 0) {
                *(float2*)(Cf + rg0 * ldc + cg) = make_float2(v00, v01);
                *(float2*)(Cf + rg1 * ldc + cg) = make_float2(v10, v11);
            } else if (MODE == 1) {
                __nv_bfloat16 h0, l0, h1, l1;
                split2(v00, h0, l0); split2(v01, h1, l1);
                *(__nv_bfloat162*)(Ch + rg0 * ldc + cg) = __halves2bfloat162(h0, h1);
                *(__nv_bfloat162*)(Cl + rg0 * ldc + cg) = __halves2bfloat162(l0, l1);
                split2(v10, h0, l0); split2(v11, h1, l1);
                *(__nv_bfloat162*)(Ch + rg1 * ldc + cg) = __halves2bfloat162(h0, h1);
                *(__nv_bfloat162*)(Cl + rg1 * ldc + cg) = __halves2bfloat162(l0, l1);
            } else {
                __nv_bfloat16 h, l;
                split2(v00, h, l);
                Ch[(long long)cg * ldc + rg0] = h; Cl[(long long)cg * ldc + rg0] = l;
                split2(v01, h, l);
                Ch[(long long)(cg + 1) * ldc + rg0] = h; Cl[(long long)(cg + 1) * ldc + rg0] = l;
                split2(v10, h, l);
                Ch[(long long)cg * ldc + rg1] = h; Cl[(long long)cg * ldc + rg1] = l;
                split2(v11, h, l);
                Ch[(long long)(cg + 1) * ldc + rg1] = h; Cl[(long long)(cg + 1) * ldc + rg1] = l;
            }
        }
    }
}

// ---------------------------------------------------------------------------
// Row softmax over fp32 scores -> split bf16 probabilities (pad keys zeroed)
// ---------------------------------------------------------------------------
__global__ void softmax_split(const float* __restrict__ S,
                              __nv_bfloat16* __restrict__ Ph,
                              __nv_bfloat16* __restrict__ Pl, int n, int npad)
{
    const long long roff = ((long long)blockIdx.y * npad + blockIdx.x) * npad;
    const float* row = S + roff;
    __nv_bfloat16* ph = Ph + roff;
    __nv_bfloat16* pl = Pl + roff;
    const int t = threadIdx.x;
    __shared__ float red[256];

    float m = -1e30f;
    for (int j = t; j < n; j += 256) m = fmaxf(m, row[j]);
    red[t] = m; __syncthreads();
    for (int s = 128; s > 0; s >>= 1) {
        if (t < s) red[t] = fmaxf(red[t], red[t + s]);
        __syncthreads();
    }
    m = red[0]; __syncthreads();

    float sum = 0.f;
    for (int j = t; j < n; j += 256) sum += __expf(row[j] - m);
    red[t] = sum; __syncthreads();
    for (int s = 128; s > 0; s >>= 1) {
        if (t < s) red[t] += red[t + s];
        __syncthreads();
    }
    const float inv = 1.f / red[0];

    for (int j = t; j < npad; j += 256) {
        float p = (j < n) ? __expf(row[j] - m) * inv : 0.f;
        __nv_bfloat16 h, l;
        split2(p, h, l);
        ph[j] = h; pl[j] = l;
    }
}

// ---------------------------------------------------------------------------
// Input assembly (fused bf16 split)
// ---------------------------------------------------------------------------
__global__ void build_x0s(const float* __restrict__ seg0,
                          __nv_bfloat16* __restrict__ Xh, __nv_bfloat16* __restrict__ Xl)
{
    int b = blockIdx.y;
    long long i = (long long)blockIdx.x * 256 + threadIdx.x;
    int pos = (int)(i >> 10), d = (int)(i & 1023);
    float v = 0.f;
    if (pos >= 1 && pos <= 2048)
        v = seg0[((long long)b * 2048 + (pos - 1)) * 1024 + d];
    __nv_bfloat16 h, l; split2(v, h, l);
    Xh[(long long)b * NP * 1024 + i] = h;
    Xl[(long long)b * NP * 1024 + i] = l;
}

__global__ void build_xss(const float* __restrict__ seg1, const float* __restrict__ pe,
                          __nv_bfloat16* __restrict__ Xh, __nv_bfloat16* __restrict__ Xl)
{
    int b = blockIdx.y;
    long long i = (long long)blockIdx.x * 256 + threadIdx.x;
    int pos = (int)(i >> 10), d = (int)(i & 1023);
    float v = 0.f;
    if (pos == 0 || pos == 513) v = pe[d];
    else if (pos >= 1 && pos <= 512)
        v = seg1[((long long)b * 2048 + (pos - 1)) * 1024 + d];
    __nv_bfloat16 h, l; split2(v, h, l);
    Xh[(long long)b * NS * 1024 + i] = h;
    Xl[(long long)b * NS * 1024 + i] = l;
}

__global__ void build_x1s(const float* __restrict__ seg0, const float* __restrict__ seg1,
                          const float* __restrict__ P1,
                          __nv_bfloat16* __restrict__ Xh, __nv_bfloat16* __restrict__ Xl)
{
    int b = blockIdx.y;
    long long i = (long long)blockIdx.x * 256 + threadIdx.x;
    int pos = (int)(i >> 10), d = (int)(i & 1023);
    float v = 0.f;
    if (pos < 32)
        v = seg0[((long long)b * 2048 + (2016 + pos)) * 1024 + d];
    else if (pos == 32 || pos == 2081)
        v = P1[b * 1024 + d];
    else if (pos >= 33 && pos <= 2080)
        v = seg1[((long long)b * 2048 + (pos - 33)) * 1024 + d];
    __nv_bfloat16 h, l; split2(v, h, l);
    Xh[(long long)b * NP * 1024 + i] = h;
    Xl[(long long)b * NP * 1024 + i] = l;
}

__global__ void wsplit_t(const float* __restrict__ W,
                         __nv_bfloat16* __restrict__ WTh, __nv_bfloat16* __restrict__ WTl)
{
    long long i = (long long)blockIdx.x * 256 + threadIdx.x;  // i = k*1024+n
    int k = (int)(i >> 10), n = (int)(i & 1023);
    float v = W[i];
    __nv_bfloat16 h, l; split2(v, h, l);
    WTh[(long long)n * 1024 + k] = h;
    WTl[(long long)n * 1024 + k] = l;
}

__global__ void copy_out(const float* __restrict__ H, float* __restrict__ out,
                         int tokens, int npad, long long off)
{
    int b = blockIdx.y;
    long long i = (long long)blockIdx.x * 256 + threadIdx.x;
    out[off + (long long)b * tokens * 1024 + i] =
        H[(long long)b * npad * 1024 + (long long)33 * 1024 + i];
}

__global__ void copy_pad128(const float* __restrict__ H, float* __restrict__ dst,
                            int npad, int token)
{
    long long i = (long long)blockIdx.x * 256 + threadIdx.x;
    int r = (int)(i >> 10), d = (int)(i & 1023);
    dst[i] = (r < Bn) ? H[((long long)r * npad + token) * 1024 + d] : 0.f;
}

// ---------------------------------------------------------------------------
// fp32 fallback SGEMM (stage C only; tiny)
// ---------------------------------------------------------------------------
template <bool TRANSB, bool BIAS>
__global__ void __launch_bounds__(256)
sgemm(const float* __restrict__ A, const float* __restrict__ Bm,
      float* __restrict__ C, const float* __restrict__ bias,
      int N, int Kd, float scale)
{
    __shared__ float As[8][128];
    __shared__ float Bs[8][128];
    const int t = threadIdx.x, tx = t & 15, ty = t >> 4;
    const int row0 = blockIdx.y * 128, col0 = blockIdx.x * 128;
    const int aRow = t >> 1, aCol = (t & 1) << 2;
    const int bRow = t >> 5, bCol = (t & 31) << 2;
    float acc[8][8];
#pragma unroll
    for (int i = 0; i < 8; i++)
#pragma unroll
        for (int j = 0; j < 8; j++) acc[i][j] = 0.f;
    const float* Aptr = A + (long long)(row0 + aRow) * Kd + aCol;
    const float* Bptr = TRANSB ? (Bm + (long long)(col0 + aRow) * Kd + aCol)
                               : (Bm + (long long)bRow * N + col0 + bCol);
    for (int k0 = 0; k0 < Kd; k0 += 8) {
        float4 av = *(const float4*)(Aptr + k0);
        As[aCol + 0][aRow] = av.x; As[aCol + 1][aRow] = av.y;
        As[aCol + 2][aRow] = av.z; As[aCol + 3][aRow] = av.w;
        if (TRANSB) {
            float4 bv = *(const float4*)(Bptr + k0);
            Bs[aCol + 0][aRow] = bv.x; Bs[aCol + 1][aRow] = bv.y;
            Bs[aCol + 2][aRow] = bv.z; Bs[aCol + 3][aRow] = bv.w;
        } else {
            float4 bv = *(const float4*)(Bptr + (long long)k0 * N);
            *(float4*)&Bs[bRow][bCol] = bv;
        }
        __syncthreads();
#pragma unroll
        for (int kk = 0; kk < 8; kk++) {
            float ar[8], br[8];
            *(float4*)&ar[0] = *(const float4*)&As[kk][ty * 8];
            *(float4*)&ar[4] = *(const float4*)&As[kk][ty * 8 + 4];
            *(float4*)&br[0] = *(const float4*)&Bs[kk][tx * 8];
            *(float4*)&br[4] = *(const float4*)&Bs[kk][tx * 8 + 4];
#pragma unroll
            for (int i = 0; i < 8; i++)
#pragma unroll
                for (int j = 0; j < 8; j++)
                    acc[i][j] = fmaf(ar[i], br[j], acc[i][j]);
        }
        __syncthreads();
    }
#pragma unroll
    for (int i = 0; i < 8; i++) {
        long long r = row0 + ty * 8 + i;
#pragma unroll
        for (int j = 0; j < 8; j += 4) {
            int c = col0 + tx * 8 + j;
            float4 v;
            v.x = acc[i][j + 0] * scale; v.y = acc[i][j + 1] * scale;
            v.z = acc[i][j + 2] * scale; v.w = acc[i][j + 3] * scale;
            if (BIAS) { v.x += bias[c]; v.y += bias[c + 1]; v.z += bias[c + 2]; v.w += bias[c + 3]; }
            *(float4*)(C + r * N + c) = v;
        }
    }
}

// Tiny 8-way memory attention
__global__ void mem_attn(const float* __restrict__ Qn, const float* __restrict__ Kp,
                         const float* __restrict__ M1, float* __restrict__ P1)
{
    int b = blockIdx.x, t = threadIdx.x;
    __shared__ float red[256];
    __shared__ float attn[Bn];
    for (int j = 0; j < Bn; j++) {
        float p = 0.f;
        for (int d = t; d < 1024; d += 256)
            p += Qn[b * 1024 + d] * Kp[j * 1024 + d];
        red[t] = p; __syncthreads();
        for (int s = 128; s > 0; s >>= 1) {
            if (t < s) red[t] += red[t + s];
            __syncthreads();
        }
        if (t == 0) attn[j] = red[0] * 0.03125f;
        __syncthreads();
    }
    if (t == 0) {
        float m = -1e30f;
        for (int j = 0; j < Bn; j++) m = fmaxf(m, attn[j]);
        float s = 0.f;
        for (int j = 0; j < Bn; j++) { attn[j] = __expf(attn[j] - m); s += attn[j]; }
        float inv = 1.f / s;
        for (int j = 0; j < Bn; j++) attn[j] *= inv;
    }
    __syncthreads();
    for (int d = t; d < 1024; d += 256) {
        float v = 0.f;
#pragma unroll
        for (int j = 0; j < Bn; j++) v += attn[j] * M1[j * 1024 + d];
        P1[b * 1024 + d] = v;
    }
}

// ---------------------------------------------------------------------------
// Host orchestration
// ---------------------------------------------------------------------------
struct Ptrs {
    __nv_bfloat16 *Xh, *Xl, *Qh, *Ql, *Kh, *Kl, *Vth, *Vtl, *Oh, *Ol, *Ph, *Pl;
    __nv_bfloat16 *WqTh, *WqTl, *WkTh, *WkTl, *WvTh, *WvTl, *WoTh, *WoTl;
    float *S, *H, *M1, *S1, *Qn, *Kp, *P1;
};

static void run_backbone_tc(const Ptrs& p,
                            const float* bq, const float* bk,
                            const float* bv, const float* bo,
                            int n, int npad)
{
    const int mt = npad / 128;
    const long long sXD = (long long)npad * Dn;
    const long long sPP = (long long)npad * npad;
    dim3 gp(Dn / 128, mt, Bn);
    tgemm<1, true><<<gp, 256, TG_SMEM>>>(p.Xh, p.Xl, p.WqTh, p.WqTl,
        nullptr, p.Qh, p.Ql, bq, Dn, Dn, 1.f, sXD, 0, sXD);
    tgemm<1, true><<<gp, 256, TG_SMEM>>>(p.Xh, p.Xl, p.WkTh, p.WkTl,
        nullptr, p.Kh, p.Kl, bk, Dn, Dn, 1.f, sXD, 0, sXD);
    tgemm<2, true><<<gp, 256, TG_SMEM>>>(p.Xh, p.Xl, p.WvTh, p.WvTl,
        nullptr, p.Vth, p.Vtl, bv, Dn, npad, 1.f, sXD, 0, sXD);
    dim3 gs(mt, mt, Bn);
    tgemm<0, false><<<gs, 256, TG_SMEM>>>(p.Qh, p.Ql, p.Kh, p.Kl,
        p.S, nullptr, nullptr, nullptr, Dn, npad, 0.03125f, sXD, sXD, sPP);
    softmax_split<<<dim3(n, Bn), 256>>>(p.S, p.Ph, p.Pl, n, npad);
    tgemm<1, false><<<gp, 256, TG_SMEM>>>(p.Ph, p.Pl, p.Vth, p.Vtl,
        nullptr, p.Oh, p.Ol, nullptr, npad, Dn, 1.f, sPP, sXD, sXD);
    tgemm<0, true><<<gp, 256, TG_SMEM>>>(p.Oh, p.Ol, p.WoTh, p.WoTl,
        p.H, nullptr, nullptr, bo, Dn, Dn, 1.f, sXD, 0, sXD);
}

extern "C" void kernel_launch(void* const* d_in, const int* in_sizes, int n_in,
                              void* d_out, int out_size)
{
    const float* seg0   = (const float*)d_in[0];
    const float* seg1   = (const float*)d_in[1];
    const float* pe     = (const float*)d_in[2];
    const float* Wq_mem = (const float*)d_in[3];
    const float* bq_mem = (const float*)d_in[4];
    const float* Wk_mem = (const float*)d_in[5];
    const float* bk_mem = (const float*)d_in[6];
    const float* Wq     = (const float*)d_in[7];
    const float* bq     = (const float*)d_in[8];
    const float* Wk     = (const float*)d_in[9];
    const float* bk     = (const float*)d_in[10];
    const float* Wv     = (const float*)d_in[11];
    const float* bv     = (const float*)d_in[12];
    const float* Wo     = (const float*)d_in[13];
    const float* bo     = (const float*)d_in[14];
    float* out = (float*)d_out;

    cudaFuncSetAttribute(tgemm<0, false>, cudaFuncAttributeMaxDynamicSharedMemorySize, TG_SMEM);
    cudaFuncSetAttribute(tgemm<0, true>,  cudaFuncAttributeMaxDynamicSharedMemorySize, TG_SMEM);
    cudaFuncSetAttribute(tgemm<1, false>, cudaFuncAttributeMaxDynamicSharedMemorySize, TG_SMEM);
    cudaFuncSetAttribute(tgemm<1, true>,  cudaFuncAttributeMaxDynamicSharedMemorySize, TG_SMEM);
    cudaFuncSetAttribute(tgemm<2, true>,  cudaFuncAttributeMaxDynamicSharedMemorySize, TG_SMEM);

    Ptrs p;
    cudaGetSymbolAddress((void**)&p.Xh, g_Xh);   cudaGetSymbolAddress((void**)&p.Xl, g_Xl);
    cudaGetSymbolAddress((void**)&p.Qh, g_Qh);   cudaGetSymbolAddress((void**)&p.Ql, g_Ql);
    cudaGetSymbolAddress((void**)&p.Kh, g_Kh);   cudaGetSymbolAddress((void**)&p.Kl, g_Kl);
    cudaGetSymbolAddress((void**)&p.Vth, g_Vth); cudaGetSymbolAddress((void**)&p.Vtl, g_Vtl);
    cudaGetSymbolAddress((void**)&p.Oh, g_Oh);   cudaGetSymbolAddress((void**)&p.Ol, g_Ol);
    cudaGetSymbolAddress((void**)&p.Ph, g_Ph);   cudaGetSymbolAddress((void**)&p.Pl, g_Pl);
    cudaGetSymbolAddress((void**)&p.WqTh, g_WqTh); cudaGetSymbolAddress((void**)&p.WqTl, g_WqTl);
    cudaGetSymbolAddress((void**)&p.WkTh, g_WkTh); cudaGetSymbolAddress((void**)&p.WkTl, g_WkTl);
    cudaGetSymbolAddress((void**)&p.WvTh, g_WvTh); cudaGetSymbolAddress((void**)&p.WvTl, g_WvTl);
    cudaGetSymbolAddress((void**)&p.WoTh, g_WoTh); cudaGetSymbolAddress((void**)&p.WoTl, g_WoTl);
    cudaGetSymbolAddress((void**)&p.S, g_S);     cudaGetSymbolAddress((void**)&p.H, g_H);
    cudaGetSymbolAddress((void**)&p.M1, g_M1);   cudaGetSymbolAddress((void**)&p.S1, g_S1);
    cudaGetSymbolAddress((void**)&p.Qn, g_Qn);   cudaGetSymbolAddress((void**)&p.Kp, g_Kp);
    cudaGetSymbolAddress((void**)&p.P1, g_P1);

    const int WG = Dn * Dn / 256;
    wsplit_t<<<WG, 256>>>(Wq, p.WqTh, p.WqTl);
    wsplit_t<<<WG, 256>>>(Wk, p.WkTh, p.WkTl);
    wsplit_t<<<WG, 256>>>(Wv, p.WvTh, p.WvTl);
    wsplit_t<<<WG, 256>>>(Wo, p.WoTh, p.WoTl);

    // ---- Stage A: backbone over input_h0 (n = 2050) ----
    build_x0s<<<dim3(NP * Dn / 256, Bn), 256>>>(seg0, p.Xh, p.Xl);
    run_backbone_tc(p, bq, bk, bv, bo, 2050, NP);
    copy_out<<<dim3(2016 * Dn / 256, Bn), 256>>>(p.H, out, 2016, NP, 0LL);
    copy_pad128<<<dim3(128 * Dn / 256), 256>>>(p.H, p.M1, NP, 2049);

    // ---- Stage B: summarize(seg1) (n = 514) ----
    build_xss<<<dim3(NS * Dn / 256, Bn), 256>>>(seg1, pe, p.Xh, p.Xl);
    run_backbone_tc(p, bq, bk, bv, bo, 514, NS);
    copy_pad128<<<dim3(128 * Dn / 256), 256>>>(p.H, p.S1, NS, 512);

    // ---- Stage C: memory attention (tiny, fp32 path) ----
    dim3 gMem(Dn / 128, 1, 1);
    sgemm<false, true><<<gMem, 256>>>(p.S1, Wq_mem, p.Qn, bq_mem, Dn, Dn, 1.f);
    sgemm<false, true><<<gMem, 256>>>(p.M1, Wk_mem, p.Kp, bk_mem, Dn, Dn, 1.f);
    mem_attn<<<Bn, 256>>>(p.Qn, p.Kp, p.M1, p.P1);

    // ---- Stage D: backbone over input_h1 (n = 2082) ----
    build_x1s<<<dim3(NP * Dn / 256, Bn), 256>>>(seg0, seg1, p.P1, p.Xh, p.Xl);
    run_backbone_tc(p, bq, bk, bv, bo, 2082, NP);
    copy_out<<<dim3(2048 * Dn / 256, Bn), 256>>>(p.H, out, 2048, NP,
                                                 (long long)Bn * 2016 * Dn);
}

// round 4
// speedup vs baseline: 2.9246x; 1.0076x over previous
#include <cuda_runtime.h>
#include <cuda_bf16.h>
#include <math.h>
#include <cstdint>

// ---------------------------------------------------------------------------
// Problem constants: B=8, L=2048, D=1024, K=32, J=512
//   backbone0 n=2050, summarize n=514, backbone1 n=2082
//   Pad to NP=2176 (17*128) and NS=640 (5*128).
// ---------------------------------------------------------------------------
#define Bn 8
#define Dn 1024
#define NP 2176
#define NS 640

#define EL_XD ((size_t)Bn * NP * Dn)
#define EL_PP ((size_t)Bn * NP * NP)

__device__ __align__(256) __nv_bfloat16 g_Xh[EL_XD], g_Xl[EL_XD];
__device__ __align__(256) __nv_bfloat16 g_Qh[EL_XD], g_Ql[EL_XD];
__device__ __align__(256) __nv_bfloat16 g_Kh[EL_XD], g_Kl[EL_XD];
__device__ __align__(256) __nv_bfloat16 g_Vth[EL_XD], g_Vtl[EL_XD]; // V transposed
__device__ __align__(256) __nv_bfloat16 g_Oh[EL_XD], g_Ol[EL_XD];
__device__ __align__(256) __nv_bfloat16 g_Ph[EL_PP], g_Pl[EL_PP];
__device__ __align__(256) float g_S[EL_PP];
__device__ __align__(256) float g_H[EL_XD];
__device__ __align__(256) __nv_bfloat16 g_WqTh[Dn*Dn], g_WqTl[Dn*Dn];
__device__ __align__(256) __nv_bfloat16 g_WkTh[Dn*Dn], g_WkTl[Dn*Dn];
__device__ __align__(256) __nv_bfloat16 g_WvTh[Dn*Dn], g_WvTl[Dn*Dn];
__device__ __align__(256) __nv_bfloat16 g_WoTh[Dn*Dn], g_WoTl[Dn*Dn];
__device__ __align__(256) float g_M1[128 * Dn];
__device__ __align__(256) float g_S1[128 * Dn];
__device__ __align__(256) float g_Qn[128 * Dn];
__device__ __align__(256) float g_Kp[128 * Dn];
__device__ __align__(256) float g_P1[Bn * Dn];

// ---------------------------------------------------------------------------
// helpers
// ---------------------------------------------------------------------------
__device__ __forceinline__ uint32_t smem_u32(const void* p) {
    uint32_t a;
    asm("{ .reg .u64 t; cvta.to.shared.u64 t, %1; cvt.u32.u64 %0, t; }"
        : "=r"(a) : "l"(p));
    return a;
}
__device__ __forceinline__ void split2(float v, __nv_bfloat16& h, __nv_bfloat16& l) {
    h = __float2bfloat16_rn(v);
    l = __float2bfloat16_rn(v - __bfloat162float(h));
}
// swizzle for [128 rows][32 bf16] tiles (64B rows), 16B chunk c in [0,4):
// phys = row*64 + ((c ^ (row>>1)) & 3) * 16  -> each 8-row ldmatrix phase
// hits 8 distinct 16B slots within the 128B bank window (even rows half0,
// odd rows half1, chunk index cycles with row>>1).
__device__ __forceinline__ uint32_t swz32(int row, int c16) {
    return ((uint32_t)row << 6) | ((uint32_t)((c16 ^ (row >> 1)) & 3) << 4);
}
__device__ __forceinline__ void ldsm4(uint32_t* r, uint32_t addr) {
    asm volatile("ldmatrix.sync.aligned.m8n8.x4.shared.b16 {%0,%1,%2,%3}, [%4];"
        : "=r"(r[0]), "=r"(r[1]), "=r"(r[2]), "=r"(r[3]) : "r"(addr));
}
__device__ __forceinline__ void mma_bf16(float* d, const uint32_t* a, const uint32_t* b) {
    asm volatile(
        "mma.sync.aligned.m16n8k16.row.col.f32.bf16.bf16.f32 "
        "{%0,%1,%2,%3}, {%4,%5,%6,%7}, {%8,%9}, {%0,%1,%2,%3};"
        : "+f"(d[0]), "+f"(d[1]), "+f"(d[2]), "+f"(d[3])
        : "r"(a[0]), "r"(a[1]), "r"(a[2]), "r"(a[3]), "r"(b[0]), "r"(b[1]));
}

// ---------------------------------------------------------------------------
// split-bf16 tensor-core GEMM: C = scale*(Ah+Al)*(Bh+Bl)^T (+bias over cols)
//   CTA tile 128x128, warp tile 64x32 (8 warps 2x4), K-chunk 32,
//   3-stage cp.async ring (96KB smem -> 2 CTAs/SM), fp32 accum.
//   MODE 0: fp32 out; MODE 1: split bf16 out; MODE 2: split bf16 TRANSPOSED.
//   Batched via blockIdx.z (element strides sA, sB, sC).
// ---------------------------------------------------------------------------
#define STAGE_B 32768            // 4 tiles x 8KB
#define TG_SMEM (3 * STAGE_B)    // 98304 bytes

__device__ __forceinline__ void fill_chunk(uint32_t sm,
    const __nv_bfloat16* Ah, const __nv_bfloat16* Al,
    const __nv_bfloat16* Bh, const __nv_bfloat16* Bl,
    int Kd, int t, int c)
{
    long long k0 = (long long)c << 5;
#pragma unroll
    for (int i = 0; i < 2; i++) {
        int p = t + (i << 8);            // 0..511 = row*4 + chunk
        int row = p >> 2;
        int cc  = p & 3;
        uint32_t so = swz32(row, cc);
        long long go = (long long)row * Kd + k0 + ((long long)cc << 3);
        asm volatile("cp.async.cg.shared.global [%0], [%1], 16;"
                     :: "r"(sm + so), "l"(Ah + go));
        asm volatile("cp.async.cg.shared.global [%0], [%1], 16;"
                     :: "r"(sm + 8192u + so), "l"(Al + go));
        asm volatile("cp.async.cg.shared.global [%0], [%1], 16;"
                     :: "r"(sm + 16384u + so), "l"(Bh + go));
        asm volatile("cp.async.cg.shared.global [%0], [%1], 16;"
                     :: "r"(sm + 24576u + so), "l"(Bl + go));
    }
}

template <int MODE, bool BIAS>
__global__ void __launch_bounds__(256, 2)
tgemm(const __nv_bfloat16* __restrict__ Ah, const __nv_bfloat16* __restrict__ Al,
      const __nv_bfloat16* __restrict__ Bh, const __nv_bfloat16* __restrict__ Bl,
      float* __restrict__ Cf, __nv_bfloat16* __restrict__ Ch,
      __nv_bfloat16* __restrict__ Cl, const float* __restrict__ bias,
      int Kd, int ldc, float scale,
      long long sA, long long sB, long long sC)
{
    extern __shared__ __align__(1024) char smem[];
    const int tid = threadIdx.x, wid = tid >> 5, lane = tid & 31;
    const long long z = blockIdx.z;
    Ah += z * sA; Al += z * sA; Bh += z * sB; Bl += z * sB;
    if (MODE == 0) Cf += z * sC; else { Ch += z * sC; Cl += z * sC; }

    const uint32_t sb = smem_u32(smem);
    const __nv_bfloat16* At_h = Ah + (long long)blockIdx.y * 128 * Kd;
    const __nv_bfloat16* At_l = Al + (long long)blockIdx.y * 128 * Kd;
    const __nv_bfloat16* Bt_h = Bh + (long long)blockIdx.x * 128 * Kd;
    const __nv_bfloat16* Bt_l = Bl + (long long)blockIdx.x * 128 * Kd;

    const int wr = wid >> 2, wc = wid & 3;    // 2 x 4 warp grid
    const int m0 = wr * 64, n0 = wc * 32;

    float acc[4][4][4];
#pragma unroll
    for (int i = 0; i < 4; i++)
#pragma unroll
        for (int j = 0; j < 4; j++)
#pragma unroll
            for (int r = 0; r < 4; r++) acc[i][j][r] = 0.f;

    const int NC = Kd >> 5;
    fill_chunk(sb, At_h, At_l, Bt_h, Bt_l, Kd, tid, 0);
    asm volatile("cp.async.commit_group;");
    fill_chunk(sb + STAGE_B, At_h, At_l, Bt_h, Bt_l, Kd, tid, 1);
    asm volatile("cp.async.commit_group;");

#pragma unroll 1
    for (int c = 0; c < NC; c++) {
        if (c == NC - 1) asm volatile("cp.async.wait_group 0;");
        else             asm volatile("cp.async.wait_group 1;");
        __syncthreads();   // fill(c) visible to all; compute(c-1) done by all

        const uint32_t tb  = sb + (uint32_t)(c % 3) * STAGE_B;
        const uint32_t aAh = tb, aAl = tb + 8192u;
        const uint32_t aBh = tb + 16384u, aBl = tb + 24576u;

#pragma unroll
        for (int kk = 0; kk < 2; kk++) {
            const int k16 = kk << 1;  // 16B-chunk base of this 16-K step
            uint32_t Bhf[2][4], Blf[2][4];
            const int br = n0 + ((lane >> 4) << 3) + (lane & 7);
            const int bc = k16 + ((lane >> 3) & 1);
#pragma unroll
            for (int j2 = 0; j2 < 2; j2++) {
                const uint32_t off = swz32(br + 16 * j2, bc);
                ldsm4(Bhf[j2], aBh + off);
                ldsm4(Blf[j2], aBl + off);
            }
            const int ar = m0 + (lane & 15);
            const int ac = k16 + (lane >> 4);
#pragma unroll
            for (int ih = 0; ih < 2; ih++) {
                uint32_t Ahf[2][4], Alf[2][4];
#pragma unroll
                for (int ii = 0; ii < 2; ii++) {
                    const uint32_t off = swz32(ar + 16 * (2 * ih + ii), ac);
                    ldsm4(Ahf[ii], aAh + off);
                    ldsm4(Alf[ii], aAl + off);
                }
#pragma unroll
                for (int ii = 0; ii < 2; ii++) {
                    const int i = 2 * ih + ii;
#pragma unroll
                    for (int jt = 0; jt < 4; jt++) {
                        const uint32_t* bh = &Bhf[jt >> 1][(jt & 1) << 1];
                        const uint32_t* bl = &Blf[jt >> 1][(jt & 1) << 1];
                        mma_bf16(acc[i][jt], Ahf[ii], bh);
                        mma_bf16(acc[i][jt], Alf[ii], bh);
                        mma_bf16(acc[i][jt], Ahf[ii], bl);
                    }
                }
            }
        }
        if (c + 2 < NC) {
            fill_chunk(sb + (uint32_t)((c + 2) % 3) * STAGE_B,
                       At_h, At_l, Bt_h, Bt_l, Kd, tid, c + 2);
            asm volatile("cp.async.commit_group;");
        }
    }

    // ---------------- epilogue ----------------
    const int row0 = blockIdx.y * 128, col0 = blockIdx.x * 128;
    const int rl = lane >> 2;              // 0..7
    const int cl = (lane & 3) << 1;        // 0,2,4,6
#pragma unroll
    for (int i = 0; i < 4; i++) {
        const long long rg0 = row0 + m0 + i * 16 + rl;
        const long long rg1 = rg0 + 8;
#pragma unroll
        for (int j = 0; j < 4; j++) {
            const int cg = col0 + n0 + j * 8 + cl;
            float v00 = acc[i][j][0] * scale, v01 = acc[i][j][1] * scale;
            float v10 = acc[i][j][2] * scale, v11 = acc[i][j][3] * scale;
            if (BIAS) {
                const float b0 = bias[cg], b1 = bias[cg + 1];
                v00 += b0; v01 += b1; v10 += b0; v11 += b1;
            }
            if (MODE == 0) {
                *(float2*)(Cf + rg0 * ldc + cg) = make_float2(v00, v01);
                *(float2*)(Cf + rg1 * ldc + cg) = make_float2(v10, v11);
            } else if (MODE == 1) {
                __nv_bfloat16 h0, l0, h1, l1;
                split2(v00, h0, l0); split2(v01, h1, l1);
                *(__nv_bfloat162*)(Ch + rg0 * ldc + cg) = __halves2bfloat162(h0, h1);
                *(__nv_bfloat162*)(Cl + rg0 * ldc + cg) = __halves2bfloat162(l0, l1);
                split2(v10, h0, l0); split2(v11, h1, l1);
                *(__nv_bfloat162*)(Ch + rg1 * ldc + cg) = __halves2bfloat162(h0, h1);
                *(__nv_bfloat162*)(Cl + rg1 * ldc + cg) = __halves2bfloat162(l0, l1);
            } else {
                __nv_bfloat16 h, l;
                split2(v00, h, l);
                Ch[(long long)cg * ldc + rg0] = h; Cl[(long long)cg * ldc + rg0] = l;
                split2(v01, h, l);
                Ch[(long long)(cg + 1) * ldc + rg0] = h; Cl[(long long)(cg + 1) * ldc + rg0] = l;
                split2(v10, h, l);
                Ch[(long long)cg * ldc + rg1] = h; Cl[(long long)cg * ldc + rg1] = l;
                split2(v11, h, l);
                Ch[(long long)(cg + 1) * ldc + rg1] = h; Cl[(long long)(cg + 1) * ldc + rg1] = l;
            }
        }
    }
}

// ---------------------------------------------------------------------------
// Row softmax over fp32 scores -> split bf16 probabilities (pad keys zeroed)
// ---------------------------------------------------------------------------
__global__ void softmax_split(const float* __restrict__ S,
                              __nv_bfloat16* __restrict__ Ph,
                              __nv_bfloat16* __restrict__ Pl, int n, int npad)
{
    const long long roff = ((long long)blockIdx.y * npad + blockIdx.x) * npad;
    const float* row = S + roff;
    __nv_bfloat16* ph = Ph + roff;
    __nv_bfloat16* pl = Pl + roff;
    const int t = threadIdx.x;
    __shared__ float red[256];

    float m = -1e30f;
    for (int j = t; j < n; j += 256) m = fmaxf(m, row[j]);
    red[t] = m; __syncthreads();
    for (int s = 128; s > 0; s >>= 1) {
        if (t < s) red[t] = fmaxf(red[t], red[t + s]);
        __syncthreads();
    }
    m = red[0]; __syncthreads();

    float sum = 0.f;
    for (int j = t; j < n; j += 256) sum += __expf(row[j] - m);
    red[t] = sum; __syncthreads();
    for (int s = 128; s > 0; s >>= 1) {
        if (t < s) red[t] += red[t + s];
        __syncthreads();
    }
    const float inv = 1.f / red[0];

    for (int j = t; j < npad; j += 256) {
        float p = (j < n) ? __expf(row[j] - m) * inv : 0.f;
        __nv_bfloat16 h, l;
        split2(p, h, l);
        ph[j] = h; pl[j] = l;
    }
}

// ---------------------------------------------------------------------------
// Input assembly (fused bf16 split)
// ---------------------------------------------------------------------------
__global__ void build_x0s(const float* __restrict__ seg0,
                          __nv_bfloat16* __restrict__ Xh, __nv_bfloat16* __restrict__ Xl)
{
    int b = blockIdx.y;
    long long i = (long long)blockIdx.x * 256 + threadIdx.x;
    int pos = (int)(i >> 10), d = (int)(i & 1023);
    float v = 0.f;
    if (pos >= 1 && pos <= 2048)
        v = seg0[((long long)b * 2048 + (pos - 1)) * 1024 + d];
    __nv_bfloat16 h, l; split2(v, h, l);
    Xh[(long long)b * NP * 1024 + i] = h;
    Xl[(long long)b * NP * 1024 + i] = l;
}

__global__ void build_xss(const float* __restrict__ seg1, const float* __restrict__ pe,
                          __nv_bfloat16* __restrict__ Xh, __nv_bfloat16* __restrict__ Xl)
{
    int b = blockIdx.y;
    long long i = (long long)blockIdx.x * 256 + threadIdx.x;
    int pos = (int)(i >> 10), d = (int)(i & 1023);
    float v = 0.f;
    if (pos == 0 || pos == 513) v = pe[d];
    else if (pos >= 1 && pos <= 512)
        v = seg1[((long long)b * 2048 + (pos - 1)) * 1024 + d];
    __nv_bfloat16 h, l; split2(v, h, l);
    Xh[(long long)b * NS * 1024 + i] = h;
    Xl[(long long)b * NS * 1024 + i] = l;
}

__global__ void build_x1s(const float* __restrict__ seg0, const float* __restrict__ seg1,
                          const float* __restrict__ P1,
                          __nv_bfloat16* __restrict__ Xh, __nv_bfloat16* __restrict__ Xl)
{
    int b = blockIdx.y;
    long long i = (long long)blockIdx.x * 256 + threadIdx.x;
    int pos = (int)(i >> 10), d = (int)(i & 1023);
    float v = 0.f;
    if (pos < 32)
        v = seg0[((long long)b * 2048 + (2016 + pos)) * 1024 + d];
    else if (pos == 32 || pos == 2081)
        v = P1[b * 1024 + d];
    else if (pos >= 33 && pos <= 2080)
        v = seg1[((long long)b * 2048 + (pos - 33)) * 1024 + d];
    __nv_bfloat16 h, l; split2(v, h, l);
    Xh[(long long)b * NP * 1024 + i] = h;
    Xl[(long long)b * NP * 1024 + i] = l;
}

__global__ void wsplit_t(const float* __restrict__ W,
                         __nv_bfloat16* __restrict__ WTh, __nv_bfloat16* __restrict__ WTl)
{
    long long i = (long long)blockIdx.x * 256 + threadIdx.x;  // i = k*1024+n
    int k = (int)(i >> 10), n = (int)(i & 1023);
    float v = W[i];
    __nv_bfloat16 h, l; split2(v, h, l);
    WTh[(long long)n * 1024 + k] = h;
    WTl[(long long)n * 1024 + k] = l;
}

__global__ void copy_out(const float* __restrict__ H, float* __restrict__ out,
                         int tokens, int npad, long long off)
{
    int b = blockIdx.y;
    long long i = (long long)blockIdx.x * 256 + threadIdx.x;
    out[off + (long long)b * tokens * 1024 + i] =
        H[(long long)b * npad * 1024 + (long long)33 * 1024 + i];
}

__global__ void copy_pad128(const float* __restrict__ H, float* __restrict__ dst,
                            int npad, int token)
{
    long long i = (long long)blockIdx.x * 256 + threadIdx.x;
    int r = (int)(i >> 10), d = (int)(i & 1023);
    dst[i] = (r < Bn) ? H[((long long)r * npad + token) * 1024 + d] : 0.f;
}

// ---------------------------------------------------------------------------
// fp32 fallback SGEMM (stage C only; tiny)
// ---------------------------------------------------------------------------
template <bool TRANSB, bool BIAS>
__global__ void __launch_bounds__(256)
sgemm(const float* __restrict__ A, const float* __restrict__ Bm,
      float* __restrict__ C, const float* __restrict__ bias,
      int N, int Kd, float scale)
{
    __shared__ float As[8][128];
    __shared__ float Bs[8][128];
    const int t = threadIdx.x, tx = t & 15, ty = t >> 4;
    const int row0 = blockIdx.y * 128, col0 = blockIdx.x * 128;
    const int aRow = t >> 1, aCol = (t & 1) << 2;
    const int bRow = t >> 5, bCol = (t & 31) << 2;
    float acc[8][8];
#pragma unroll
    for (int i = 0; i < 8; i++)
#pragma unroll
        for (int j = 0; j < 8; j++) acc[i][j] = 0.f;
    const float* Aptr = A + (long long)(row0 + aRow) * Kd + aCol;
    const float* Bptr = TRANSB ? (Bm + (long long)(col0 + aRow) * Kd + aCol)
                               : (Bm + (long long)bRow * N + col0 + bCol);
    for (int k0 = 0; k0 < Kd; k0 += 8) {
        float4 av = *(const float4*)(Aptr + k0);
        As[aCol + 0][aRow] = av.x; As[aCol + 1][aRow] = av.y;
        As[aCol + 2][aRow] = av.z; As[aCol + 3][aRow] = av.w;
        if (TRANSB) {
            float4 bv = *(const float4*)(Bptr + k0);
            Bs[aCol + 0][aRow] = bv.x; Bs[aCol + 1][aRow] = bv.y;
            Bs[aCol + 2][aRow] = bv.z; Bs[aCol + 3][aRow] = bv.w;
        } else {
            float4 bv = *(const float4*)(Bptr + (long long)k0 * N);
            *(float4*)&Bs[bRow][bCol] = bv;
        }
        __syncthreads();
#pragma unroll
        for (int kk = 0; kk < 8; kk++) {
            float ar[8], br[8];
            *(float4*)&ar[0] = *(const float4*)&As[kk][ty * 8];
            *(float4*)&ar[4] = *(const float4*)&As[kk][ty * 8 + 4];
            *(float4*)&br[0] = *(const float4*)&Bs[kk][tx * 8];
            *(float4*)&br[4] = *(const float4*)&Bs[kk][tx * 8 + 4];
#pragma unroll
            for (int i = 0; i < 8; i++)
#pragma unroll
                for (int j = 0; j < 8; j++)
                    acc[i][j] = fmaf(ar[i], br[j], acc[i][j]);
        }
        __syncthreads();
    }
#pragma unroll
    for (int i = 0; i < 8; i++) {
        long long r = row0 + ty * 8 + i;
#pragma unroll
        for (int j = 0; j < 8; j += 4) {
            int c = col0 + tx * 8 + j;
            float4 v;
            v.x = acc[i][j + 0] * scale; v.y = acc[i][j + 1] * scale;
            v.z = acc[i][j + 2] * scale; v.w = acc[i][j + 3] * scale;
            if (BIAS) { v.x += bias[c]; v.y += bias[c + 1]; v.z += bias[c + 2]; v.w += bias[c + 3]; }
            *(float4*)(C + r * N + c) = v;
        }
    }
}

// Tiny 8-way memory attention
__global__ void mem_attn(const float* __restrict__ Qn, const float* __restrict__ Kp,
                         const float* __restrict__ M1, float* __restrict__ P1)
{
    int b = blockIdx.x, t = threadIdx.x;
    __shared__ float red[256];
    __shared__ float attn[Bn];
    for (int j = 0; j < Bn; j++) {
        float p = 0.f;
        for (int d = t; d < 1024; d += 256)
            p += Qn[b * 1024 + d] * Kp[j * 1024 + d];
        red[t] = p; __syncthreads();
        for (int s = 128; s > 0; s >>= 1) {
            if (t < s) red[t] += red[t + s];
            __syncthreads();
        }
        if (t == 0) attn[j] = red[0] * 0.03125f;
        __syncthreads();
    }
    if (t == 0) {
        float m = -1e30f;
        for (int j = 0; j < Bn; j++) m = fmaxf(m, attn[j]);
        float s = 0.f;
        for (int j = 0; j < Bn; j++) { attn[j] = __expf(attn[j] - m); s += attn[j]; }
        float inv = 1.f / s;
        for (int j = 0; j < Bn; j++) attn[j] *= inv;
    }
    __syncthreads();
    for (int d = t; d < 1024; d += 256) {
        float v = 0.f;
#pragma unroll
        for (int j = 0; j < Bn; j++) v += attn[j] * M1[j * 1024 + d];
        P1[b * 1024 + d] = v;
    }
}

// ---------------------------------------------------------------------------
// Host orchestration
// ---------------------------------------------------------------------------
struct Ptrs {
    __nv_bfloat16 *Xh, *Xl, *Qh, *Ql, *Kh, *Kl, *Vth, *Vtl, *Oh, *Ol, *Ph, *Pl;
    __nv_bfloat16 *WqTh, *WqTl, *WkTh, *WkTl, *WvTh, *WvTl, *WoTh, *WoTl;
    float *S, *H, *M1, *S1, *Qn, *Kp, *P1;
};

static void run_backbone_tc(const Ptrs& p,
                            const float* bq, const float* bk,
                            const float* bv, const float* bo,
                            int n, int npad)
{
    const int mt = npad / 128;
    const long long sXD = (long long)npad * Dn;
    const long long sPP = (long long)npad * npad;
    dim3 gp(Dn / 128, mt, Bn);
    tgemm<1, true><<<gp, 256, TG_SMEM>>>(p.Xh, p.Xl, p.WqTh, p.WqTl,
        nullptr, p.Qh, p.Ql, bq, Dn, Dn, 1.f, sXD, 0, sXD);
    tgemm<1, true><<<gp, 256, TG_SMEM>>>(p.Xh, p.Xl, p.WkTh, p.WkTl,
        nullptr, p.Kh, p.Kl, bk, Dn, Dn, 1.f, sXD, 0, sXD);
    tgemm<2, true><<<gp, 256, TG_SMEM>>>(p.Xh, p.Xl, p.WvTh, p.WvTl,
        nullptr, p.Vth, p.Vtl, bv, Dn, npad, 1.f, sXD, 0, sXD);
    dim3 gs(mt, mt, Bn);
    tgemm<0, false><<<gs, 256, TG_SMEM>>>(p.Qh, p.Ql, p.Kh, p.Kl,
        p.S, nullptr, nullptr, nullptr, Dn, npad, 0.03125f, sXD, sXD, sPP);
    softmax_split<<<dim3(n, Bn), 256>>>(p.S, p.Ph, p.Pl, n, npad);
    tgemm<1, false><<<gp, 256, TG_SMEM>>>(p.Ph, p.Pl, p.Vth, p.Vtl,
        nullptr, p.Oh, p.Ol, nullptr, npad, Dn, 1.f, sPP, sXD, sXD);
    tgemm<0, true><<<gp, 256, TG_SMEM>>>(p.Oh, p.Ol, p.WoTh, p.WoTl,
        p.H, nullptr, nullptr, bo, Dn, Dn, 1.f, sXD, 0, sXD);
}

extern "C" void kernel_launch(void* const* d_in, const int* in_sizes, int n_in,
                              void* d_out, int out_size)
{
    const float* seg0   = (const float*)d_in[0];
    const float* seg1   = (const float*)d_in[1];
    const float* pe     = (const float*)d_in[2];
    const float* Wq_mem = (const float*)d_in[3];
    const float* bq_mem = (const float*)d_in[4];
    const float* Wk_mem = (const float*)d_in[5];
    const float* bk_mem = (const float*)d_in[6];
    const float* Wq     = (const float*)d_in[7];
    const float* bq     = (const float*)d_in[8];
    const float* Wk     = (const float*)d_in[9];
    const float* bk     = (const float*)d_in[10];
    const float* Wv     = (const float*)d_in[11];
    const float* bv     = (const float*)d_in[12];
    const float* Wo     = (const float*)d_in[13];
    const float* bo     = (const float*)d_in[14];
    float* out = (float*)d_out;

    cudaFuncSetAttribute(tgemm<0, false>, cudaFuncAttributeMaxDynamicSharedMemorySize, TG_SMEM);
    cudaFuncSetAttribute(tgemm<0, true>,  cudaFuncAttributeMaxDynamicSharedMemorySize, TG_SMEM);
    cudaFuncSetAttribute(tgemm<1, false>, cudaFuncAttributeMaxDynamicSharedMemorySize, TG_SMEM);
    cudaFuncSetAttribute(tgemm<1, true>,  cudaFuncAttributeMaxDynamicSharedMemorySize, TG_SMEM);
    cudaFuncSetAttribute(tgemm<2, true>,  cudaFuncAttributeMaxDynamicSharedMemorySize, TG_SMEM);

    Ptrs p;
    cudaGetSymbolAddress((void**)&p.Xh, g_Xh);   cudaGetSymbolAddress((void**)&p.Xl, g_Xl);
    cudaGetSymbolAddress((void**)&p.Qh, g_Qh);   cudaGetSymbolAddress((void**)&p.Ql, g_Ql);
    cudaGetSymbolAddress((void**)&p.Kh, g_Kh);   cudaGetSymbolAddress((void**)&p.Kl, g_Kl);
    cudaGetSymbolAddress((void**)&p.Vth, g_Vth); cudaGetSymbolAddress((void**)&p.Vtl, g_Vtl);
    cudaGetSymbolAddress((void**)&p.Oh, g_Oh);   cudaGetSymbolAddress((void**)&p.Ol, g_Ol);
    cudaGetSymbolAddress((void**)&p.Ph, g_Ph);   cudaGetSymbolAddress((void**)&p.Pl, g_Pl);
    cudaGetSymbolAddress((void**)&p.WqTh, g_WqTh); cudaGetSymbolAddress((void**)&p.WqTl, g_WqTl);
    cudaGetSymbolAddress((void**)&p.WkTh, g_WkTh); cudaGetSymbolAddress((void**)&p.WkTl, g_WkTl);
    cudaGetSymbolAddress((void**)&p.WvTh, g_WvTh); cudaGetSymbolAddress((void**)&p.WvTl, g_WvTl);
    cudaGetSymbolAddress((void**)&p.WoTh, g_WoTh); cudaGetSymbolAddress((void**)&p.WoTl, g_WoTl);
    cudaGetSymbolAddress((void**)&p.S, g_S);     cudaGetSymbolAddress((void**)&p.H, g_H);
    cudaGetSymbolAddress((void**)&p.M1, g_M1);   cudaGetSymbolAddress((void**)&p.S1, g_S1);
    cudaGetSymbolAddress((void**)&p.Qn, g_Qn);   cudaGetSymbolAddress((void**)&p.Kp, g_Kp);
    cudaGetSymbolAddress((void**)&p.P1, g_P1);

    const int WG = Dn * Dn / 256;
    wsplit_t<<<WG, 256>>>(Wq, p.WqTh, p.WqTl);
    wsplit_t<<<WG, 256>>>(Wk, p.WkTh, p.WkTl);
    wsplit_t<<<WG, 256>>>(Wv, p.WvTh, p.WvTl);
    wsplit_t<<<WG, 256>>>(Wo, p.WoTh, p.WoTl);

    // ---- Stage A: backbone over input_h0 (n = 2050) ----
    build_x0s<<<dim3(NP * Dn / 256, Bn), 256>>>(seg0, p.Xh, p.Xl);
    run_backbone_tc(p, bq, bk, bv, bo, 2050, NP);
    copy_out<<<dim3(2016 * Dn / 256, Bn), 256>>>(p.H, out, 2016, NP, 0LL);
    copy_pad128<<<dim3(128 * Dn / 256), 256>>>(p.H, p.M1, NP, 2049);

    // ---- Stage B: summarize(seg1) (n = 514) ----
    build_xss<<<dim3(NS * Dn / 256, Bn), 256>>>(seg1, pe, p.Xh, p.Xl);
    run_backbone_tc(p, bq, bk, bv, bo, 514, NS);
    copy_pad128<<<dim3(128 * Dn / 256), 256>>>(p.H, p.S1, NS, 512);

    // ---- Stage C: memory attention (tiny, fp32 path) ----
    dim3 gMem(Dn / 128, 1, 1);
    sgemm<false, true><<<gMem, 256>>>(p.S1, Wq_mem, p.Qn, bq_mem, Dn, Dn, 1.f);
    sgemm<false, true><<<gMem, 256>>>(p.M1, Wk_mem, p.Kp, bk_mem, Dn, Dn, 1.f);
    mem_attn<<<Bn, 256>>>(p.Qn, p.Kp, p.M1, p.P1);

    // ---- Stage D: backbone over input_h1 (n = 2082) ----
    build_x1s<<<dim3(NP * Dn / 256, Bn), 256>>>(seg0, seg1, p.P1, p.Xh, p.Xl);
    run_backbone_tc(p, bq, bk, bv, bo, 2082, NP);
    copy_out<<<dim3(2048 * Dn / 256, Bn), 256>>>(p.H, out, 2048, NP,
                                                 (long long)Bn * 2016 * Dn);
}

// round 5
// speedup vs baseline: 6.4706x; 2.2125x over previous
#include <cuda_runtime.h>
#include <cuda_fp16.h>
#include <math.h>
#include <cstdint>

// ---------------------------------------------------------------------------
// Problem constants: B=8, L=2048, D=1024, K=32, J=512
//   backbone0 n=2050, summarize n=514, backbone1 n=2082
//   Pad to NP=2176 (17*128) and NS=640 (5*128).
// ---------------------------------------------------------------------------
#define Bn 8
#define Dn 1024
#define NP 2176
#define NS 640

#define EL_XD ((size_t)Bn * NP * Dn)
#define EL_PP ((size_t)Bn * NP * NP)

__device__ __align__(256) __half g_X[EL_XD];
__device__ __align__(256) __half g_Q[EL_XD];
__device__ __align__(256) __half g_K[EL_XD];
__device__ __align__(256) __half g_Vt[EL_XD];   // V transposed [d][token]
__device__ __align__(256) __half g_O[EL_XD];
__device__ __align__(256) __half g_P[EL_PP];
__device__ __align__(256) float  g_S[EL_PP];
__device__ __align__(256) float  g_H[EL_XD];
__device__ __align__(256) __half g_WqT[Dn*Dn], g_WkT[Dn*Dn], g_WvT[Dn*Dn], g_WoT[Dn*Dn];
// stage C fp32 scratch
__device__ __align__(256) float g_M1[128 * Dn];
__device__ __align__(256) float g_S1[128 * Dn];
__device__ __align__(256) float g_Qn[128 * Dn];
__device__ __align__(256) float g_Kp[128 * Dn];
__device__ __align__(256) float g_P1[Bn * Dn];

// ---------------------------------------------------------------------------
// helpers
// ---------------------------------------------------------------------------
__device__ __forceinline__ uint32_t smem_u32(const void* p) {
    uint32_t a;
    asm("{ .reg .u64 t; cvta.to.shared.u64 t, %1; cvt.u32.u64 %0, t; }"
        : "=r"(a) : "l"(p));
    return a;
}
// SW128 swizzle for [row][64 half] tiles (128B rows): 16B chunk col XOR row%8
__device__ __forceinline__ uint32_t swz(int row, int col16) {
    return ((uint32_t)row << 7) | ((uint32_t)((col16 ^ row) & 7) << 4);
}
__device__ __forceinline__ void ldsm4(uint32_t* r, uint32_t addr) {
    asm volatile("ldmatrix.sync.aligned.m8n8.x4.shared.b16 {%0,%1,%2,%3}, [%4];"
        : "=r"(r[0]), "=r"(r[1]), "=r"(r[2]), "=r"(r[3]) : "r"(addr));
}
__device__ __forceinline__ void mma_f16(float* d, const uint32_t* a, const uint32_t* b) {
    asm volatile(
        "mma.sync.aligned.m16n8k16.row.col.f32.f16.f16.f32 "
        "{%0,%1,%2,%3}, {%4,%5,%6,%7}, {%8,%9}, {%0,%1,%2,%3};"
        : "+f"(d[0]), "+f"(d[1]), "+f"(d[2]), "+f"(d[3])
        : "r"(a[0]), "r"(a[1]), "r"(a[2]), "r"(a[3]), "r"(b[0]), "r"(b[1]));
}

// ---------------------------------------------------------------------------
// fp16 tensor-core GEMM: C = scale * A * B^T (+bias over cols)
//   A: [M][Kd] K-major fp16; B: [N][Kd] K-major fp16.
//   CTA tile 128x128, warp tile 64x32 (8 warps 2x4), K-chunk 64,
//   3-stage cp.async ring (96KB -> 2 CTAs/SM), fp32 accum in mma.
//   MODE 0: fp32 out; MODE 1: fp16 out; MODE 2: fp16 TRANSPOSED out.
//   Batched via blockIdx.z (element strides sA, sB, sC).
// ---------------------------------------------------------------------------
#define STAGE_B 32768            // A tile 16KB + B tile 16KB
#define TG_SMEM (3 * STAGE_B)    // 98304 bytes

__device__ __forceinline__ void fill_chunk(uint32_t sm,
    const __half* A, const __half* Bm, int Kd, int t, int c)
{
    long long k0 = (long long)c << 6;
#pragma unroll
    for (int i = 0; i < 4; i++) {
        int seg = t + (i << 8);          // 0..1023 = row*8 + chunk
        int row = seg >> 3;
        int cc  = seg & 7;
        uint32_t so = swz(row, cc);
        long long go = (long long)row * Kd + k0 + ((long long)cc << 3);
        asm volatile("cp.async.cg.shared.global [%0], [%1], 16;"
                     :: "r"(sm + so), "l"(A + go));
        asm volatile("cp.async.cg.shared.global [%0], [%1], 16;"
                     :: "r"(sm + 16384u + so), "l"(Bm + go));
    }
}

template <int MODE, bool BIAS>
__global__ void __launch_bounds__(256, 2)
tgemm(const __half* __restrict__ A, const __half* __restrict__ Bm,
      float* __restrict__ Cf, __half* __restrict__ Ch,
      const float* __restrict__ bias,
      int Kd, int ldc, float scale,
      long long sA, long long sB, long long sC)
{
    extern __shared__ __align__(1024) char smem[];
    const int tid = threadIdx.x, wid = tid >> 5, lane = tid & 31;
    const long long z = blockIdx.z;
    A += z * sA; Bm += z * sB;
    if (MODE == 0) Cf += z * sC; else Ch += z * sC;

    const uint32_t sb = smem_u32(smem);
    const __half* At = A  + (long long)blockIdx.y * 128 * Kd;
    const __half* Bt = Bm + (long long)blockIdx.x * 128 * Kd;

    const int wr = wid >> 2, wc = wid & 3;    // 2 x 4 warp grid
    const int m0 = wr * 64, n0 = wc * 32;

    float acc[4][4][4];
#pragma unroll
    for (int i = 0; i < 4; i++)
#pragma unroll
        for (int j = 0; j < 4; j++)
#pragma unroll
            for (int r = 0; r < 4; r++) acc[i][j][r] = 0.f;

    const int NC = Kd >> 6;
    fill_chunk(sb, At, Bt, Kd, tid, 0);
    asm volatile("cp.async.commit_group;");
    if (NC > 1) {
        fill_chunk(sb + STAGE_B, At, Bt, Kd, tid, 1);
        asm volatile("cp.async.commit_group;");
    }

#pragma unroll 1
    for (int c = 0; c < NC; c++) {
        if (c == NC - 1) asm volatile("cp.async.wait_group 0;");
        else             asm volatile("cp.async.wait_group 1;");
        __syncthreads();

        const uint32_t tb = sb + (uint32_t)(c % 3) * STAGE_B;
        const uint32_t aA = tb, aB = tb + 16384u;

#pragma unroll
        for (int kk = 0; kk < 4; kk++) {
            const int k16 = kk << 1;  // 16B-chunk base of this 16-K step
            uint32_t Af[4][4], Bf[2][4];
            const int ar = m0 + (lane & 15);
            const int ac = k16 + (lane >> 4);
#pragma unroll
            for (int i = 0; i < 4; i++)
                ldsm4(Af[i], aA + swz(ar + 16 * i, ac));
            const int br = n0 + ((lane >> 4) << 3) + (lane & 7);
            const int bc = k16 + ((lane >> 3) & 1);
#pragma unroll
            for (int j2 = 0; j2 < 2; j2++)
                ldsm4(Bf[j2], aB + swz(br + 16 * j2, bc));
#pragma unroll
            for (int i = 0; i < 4; i++)
#pragma unroll
                for (int jt = 0; jt < 4; jt++)
                    mma_f16(acc[i][jt], Af[i], &Bf[jt >> 1][(jt & 1) << 1]);
        }
        if (c + 2 < NC) {
            fill_chunk(sb + (uint32_t)((c + 2) % 3) * STAGE_B, At, Bt, Kd, tid, c + 2);
            asm volatile("cp.async.commit_group;");
        }
    }

    // ---------------- epilogue ----------------
    const int row0 = blockIdx.y * 128, col0 = blockIdx.x * 128;
    const int rl = lane >> 2;              // 0..7
    const int cl = (lane & 3) << 1;        // 0,2,4,6
#pragma unroll
    for (int i = 0; i < 4; i++) {
        const long long rg0 = row0 + m0 + i * 16 + rl;
        const long long rg1 = rg0 + 8;
#pragma unroll
        for (int j = 0; j < 4; j++) {
            const int cg = col0 + n0 + j * 8 + cl;
            float v00 = acc[i][j][0] * scale, v01 = acc[i][j][1] * scale;
            float v10 = acc[i][j][2] * scale, v11 = acc[i][j][3] * scale;
            if (BIAS) {
                const float b0 = bias[cg], b1 = bias[cg + 1];
                v00 += b0; v01 += b1; v10 += b0; v11 += b1;
            }
            if (MODE == 0) {
                *(float2*)(Cf + rg0 * ldc + cg) = make_float2(v00, v01);
                *(float2*)(Cf + rg1 * ldc + cg) = make_float2(v10, v11);
            } else if (MODE == 1) {
                *(__half2*)(Ch + rg0 * ldc + cg) =
                    __halves2half2(__float2half_rn(v00), __float2half_rn(v01));
                *(__half2*)(Ch + rg1 * ldc + cg) =
                    __halves2half2(__float2half_rn(v10), __float2half_rn(v11));
            } else {
                Ch[(long long)cg * ldc + rg0]       = __float2half_rn(v00);
                Ch[(long long)(cg + 1) * ldc + rg0] = __float2half_rn(v01);
                Ch[(long long)cg * ldc + rg1]       = __float2half_rn(v10);
                Ch[(long long)(cg + 1) * ldc + rg1] = __float2half_rn(v11);
            }
        }
    }
}

// ---------------------------------------------------------------------------
// Row softmax over fp32 scores -> fp16 probabilities (pad keys zeroed)
// ---------------------------------------------------------------------------
__global__ void softmax_h(const float* __restrict__ S, __half* __restrict__ P,
                          int n, int npad)
{
    const long long roff = ((long long)blockIdx.y * npad + blockIdx.x) * npad;
    const float* row = S + roff;
    __half* pr = P + roff;
    const int t = threadIdx.x;
    __shared__ float red[256];

    float m = -1e30f;
    for (int j = t; j < n; j += 256) m = fmaxf(m, row[j]);
    red[t] = m; __syncthreads();
    for (int s = 128; s > 0; s >>= 1) {
        if (t < s) red[t] = fmaxf(red[t], red[t + s]);
        __syncthreads();
    }
    m = red[0]; __syncthreads();

    float sum = 0.f;
    for (int j = t; j < n; j += 256) sum += __expf(row[j] - m);
    red[t] = sum; __syncthreads();
    for (int s = 128; s > 0; s >>= 1) {
        if (t < s) red[t] += red[t + s];
        __syncthreads();
    }
    const float inv = 1.f / red[0];

    for (int j = t; j < npad; j += 256) {
        float p = (j < n) ? __expf(row[j] - m) * inv : 0.f;
        pr[j] = __float2half_rn(p);
    }
}

// ---------------------------------------------------------------------------
// Input assembly (fp32 -> fp16)
// ---------------------------------------------------------------------------
__global__ void build_x0h(const float* __restrict__ seg0, __half* __restrict__ X)
{
    int b = blockIdx.y;
    long long i = (long long)blockIdx.x * 256 + threadIdx.x;
    int pos = (int)(i >> 10), d = (int)(i & 1023);
    float v = 0.f;
    if (pos >= 1 && pos <= 2048)
        v = seg0[((long long)b * 2048 + (pos - 1)) * 1024 + d];
    X[(long long)b * NP * 1024 + i] = __float2half_rn(v);
}

__global__ void build_xsh(const float* __restrict__ seg1, const float* __restrict__ pe,
                          __half* __restrict__ X)
{
    int b = blockIdx.y;
    long long i = (long long)blockIdx.x * 256 + threadIdx.x;
    int pos = (int)(i >> 10), d = (int)(i & 1023);
    float v = 0.f;
    if (pos == 0 || pos == 513) v = pe[d];
    else if (pos >= 1 && pos <= 512)
        v = seg1[((long long)b * 2048 + (pos - 1)) * 1024 + d];
    X[(long long)b * NS * 1024 + i] = __float2half_rn(v);
}

__global__ void build_x1h(const float* __restrict__ seg0, const float* __restrict__ seg1,
                          const float* __restrict__ P1, __half* __restrict__ X)
{
    int b = blockIdx.y;
    long long i = (long long)blockIdx.x * 256 + threadIdx.x;
    int pos = (int)(i >> 10), d = (int)(i & 1023);
    float v = 0.f;
    if (pos < 32)
        v = seg0[((long long)b * 2048 + (2016 + pos)) * 1024 + d];
    else if (pos == 32 || pos == 2081)
        v = P1[b * 1024 + d];
    else if (pos >= 33 && pos <= 2080)
        v = seg1[((long long)b * 2048 + (pos - 33)) * 1024 + d];
    X[(long long)b * NP * 1024 + i] = __float2half_rn(v);
}

// weight transpose + convert: WT[n][k] = half(W[k][n])
__global__ void wcvt_t(const float* __restrict__ W, __half* __restrict__ WT)
{
    long long i = (long long)blockIdx.x * 256 + threadIdx.x;  // i = k*1024+n
    int k = (int)(i >> 10), n = (int)(i & 1023);
    WT[(long long)n * 1024 + k] = __float2half_rn(W[i]);
}

__global__ void copy_out(const float* __restrict__ H, float* __restrict__ out,
                         int tokens, int npad, long long off)
{
    int b = blockIdx.y;
    long long i = (long long)blockIdx.x * 256 + threadIdx.x;
    out[off + (long long)b * tokens * 1024 + i] =
        H[(long long)b * npad * 1024 + (long long)33 * 1024 + i];
}

__global__ void copy_pad128(const float* __restrict__ H, float* __restrict__ dst,
                            int npad, int token)
{
    long long i = (long long)blockIdx.x * 256 + threadIdx.x;
    int r = (int)(i >> 10), d = (int)(i & 1023);
    dst[i] = (r < Bn) ? H[((long long)r * npad + token) * 1024 + d] : 0.f;
}

// ---------------------------------------------------------------------------
// fp32 fallback SGEMM (stage C only; tiny)
// ---------------------------------------------------------------------------
template <bool TRANSB, bool BIAS>
__global__ void __launch_bounds__(256)
sgemm(const float* __restrict__ A, const float* __restrict__ Bm,
      float* __restrict__ C, const float* __restrict__ bias,
      int N, int Kd, float scale)
{
    __shared__ float As[8][128];
    __shared__ float Bs[8][128];
    const int t = threadIdx.x, tx = t & 15, ty = t >> 4;
    const int row0 = blockIdx.y * 128, col0 = blockIdx.x * 128;
    const int aRow = t >> 1, aCol = (t & 1) << 2;
    const int bRow = t >> 5, bCol = (t & 31) << 2;
    float acc[8][8];
#pragma unroll
    for (int i = 0; i < 8; i++)
#pragma unroll
        for (int j = 0; j < 8; j++) acc[i][j] = 0.f;
    const float* Aptr = A + (long long)(row0 + aRow) * Kd + aCol;
    const float* Bptr = TRANSB ? (Bm + (long long)(col0 + aRow) * Kd + aCol)
                               : (Bm + (long long)bRow * N + col0 + bCol);
    for (int k0 = 0; k0 < Kd; k0 += 8) {
        float4 av = *(const float4*)(Aptr + k0);
        As[aCol + 0][aRow] = av.x; As[aCol + 1][aRow] = av.y;
        As[aCol + 2][aRow] = av.z; As[aCol + 3][aRow] = av.w;
        if (TRANSB) {
            float4 bv = *(const float4*)(Bptr + k0);
            Bs[aCol + 0][aRow] = bv.x; Bs[aCol + 1][aRow] = bv.y;
            Bs[aCol + 2][aRow] = bv.z; Bs[aCol + 3][aRow] = bv.w;
        } else {
            float4 bv = *(const float4*)(Bptr + (long long)k0 * N);
            *(float4*)&Bs[bRow][bCol] = bv;
        }
        __syncthreads();
#pragma unroll
        for (int kk = 0; kk < 8; kk++) {
            float ar[8], br[8];
            *(float4*)&ar[0] = *(const float4*)&As[kk][ty * 8];
            *(float4*)&ar[4] = *(const float4*)&As[kk][ty * 8 + 4];
            *(float4*)&br[0] = *(const float4*)&Bs[kk][tx * 8];
            *(float4*)&br[4] = *(const float4*)&Bs[kk][tx * 8 + 4];
#pragma unroll
            for (int i = 0; i < 8; i++)
#pragma unroll
                for (int j = 0; j < 8; j++)
                    acc[i][j] = fmaf(ar[i], br[j], acc[i][j]);
        }
        __syncthreads();
    }
#pragma unroll
    for (int i = 0; i < 8; i++) {
        long long r = row0 + ty * 8 + i;
#pragma unroll
        for (int j = 0; j < 8; j += 4) {
            int c = col0 + tx * 8 + j;
            float4 v;
            v.x = acc[i][j + 0] * scale; v.y = acc[i][j + 1] * scale;
            v.z = acc[i][j + 2] * scale; v.w = acc[i][j + 3] * scale;
            if (BIAS) { v.x += bias[c]; v.y += bias[c + 1]; v.z += bias[c + 2]; v.w += bias[c + 3]; }
            *(float4*)(C + r * N + c) = v;
        }
    }
}

// Tiny 8-way memory attention
__global__ void mem_attn(const float* __restrict__ Qn, const float* __restrict__ Kp,
                         const float* __restrict__ M1, float* __restrict__ P1)
{
    int b = blockIdx.x, t = threadIdx.x;
    __shared__ float red[256];
    __shared__ float attn[Bn];
    for (int j = 0; j < Bn; j++) {
        float p = 0.f;
        for (int d = t; d < 1024; d += 256)
            p += Qn[b * 1024 + d] * Kp[j * 1024 + d];
        red[t] = p; __syncthreads();
        for (int s = 128; s > 0; s >>= 1) {
            if (t < s) red[t] += red[t + s];
            __syncthreads();
        }
        if (t == 0) attn[j] = red[0] * 0.03125f;
        __syncthreads();
    }
    if (t == 0) {
        float m = -1e30f;
        for (int j = 0; j < Bn; j++) m = fmaxf(m, attn[j]);
        float s = 0.f;
        for (int j = 0; j < Bn; j++) { attn[j] = __expf(attn[j] - m); s += attn[j]; }
        float inv = 1.f / s;
        for (int j = 0; j < Bn; j++) attn[j] *= inv;
    }
    __syncthreads();
    for (int d = t; d < 1024; d += 256) {
        float v = 0.f;
#pragma unroll
        for (int j = 0; j < Bn; j++) v += attn[j] * M1[j * 1024 + d];
        P1[b * 1024 + d] = v;
    }
}

// ---------------------------------------------------------------------------
// Host orchestration
// ---------------------------------------------------------------------------
struct Ptrs {
    __half *X, *Q, *K, *Vt, *O, *P;
    __half *WqT, *WkT, *WvT, *WoT;
    float *S, *H, *M1, *S1, *Qn, *Kp, *P1;
};

static void run_backbone_tc(const Ptrs& p,
                            const float* bq, const float* bk,
                            const float* bv, const float* bo,
                            int n, int npad)
{
    const int mt = npad / 128;
    const long long sXD = (long long)npad * Dn;
    const long long sPP = (long long)npad * npad;
    dim3 gp(Dn / 128, mt, Bn);
    // projections
    tgemm<1, true><<<gp, 256, TG_SMEM>>>(p.X, p.WqT, nullptr, p.Q, bq,
                                         Dn, Dn, 1.f, sXD, 0, sXD);
    tgemm<1, true><<<gp, 256, TG_SMEM>>>(p.X, p.WkT, nullptr, p.K, bk,
                                         Dn, Dn, 1.f, sXD, 0, sXD);
    tgemm<2, true><<<gp, 256, TG_SMEM>>>(p.X, p.WvT, nullptr, p.Vt, bv,
                                         Dn, npad, 1.f, sXD, 0, sXD);
    // scores
    dim3 gs(mt, mt, Bn);
    tgemm<0, false><<<gs, 256, TG_SMEM>>>(p.Q, p.K, p.S, nullptr, nullptr,
                                          Dn, npad, 0.03125f, sXD, sXD, sPP);
    softmax_h<<<dim3(n, Bn), 256>>>(p.S, p.P, n, npad);
    // attn @ V
    tgemm<1, false><<<gp, 256, TG_SMEM>>>(p.P, p.Vt, nullptr, p.O, nullptr,
                                          npad, Dn, 1.f, sPP, sXD, sXD);
    // output proj
    tgemm<0, true><<<gp, 256, TG_SMEM>>>(p.O, p.WoT, p.H, nullptr, bo,
                                         Dn, Dn, 1.f, sXD, 0, sXD);
}

extern "C" void kernel_launch(void* const* d_in, const int* in_sizes, int n_in,
                              void* d_out, int out_size)
{
    const float* seg0   = (const float*)d_in[0];
    const float* seg1   = (const float*)d_in[1];
    const float* pe     = (const float*)d_in[2];
    const float* Wq_mem = (const float*)d_in[3];
    const float* bq_mem = (const float*)d_in[4];
    const float* Wk_mem = (const float*)d_in[5];
    const float* bk_mem = (const float*)d_in[6];
    const float* Wq     = (const float*)d_in[7];
    const float* bq     = (const float*)d_in[8];
    const float* Wk     = (const float*)d_in[9];
    const float* bk     = (const float*)d_in[10];
    const float* Wv     = (const float*)d_in[11];
    const float* bv     = (const float*)d_in[12];
    const float* Wo     = (const float*)d_in[13];
    const float* bo     = (const float*)d_in[14];
    float* out = (float*)d_out;

    cudaFuncSetAttribute(tgemm<0, false>, cudaFuncAttributeMaxDynamicSharedMemorySize, TG_SMEM);
    cudaFuncSetAttribute(tgemm<0, true>,  cudaFuncAttributeMaxDynamicSharedMemorySize, TG_SMEM);
    cudaFuncSetAttribute(tgemm<1, false>, cudaFuncAttributeMaxDynamicSharedMemorySize, TG_SMEM);
    cudaFuncSetAttribute(tgemm<1, true>,  cudaFuncAttributeMaxDynamicSharedMemorySize, TG_SMEM);
    cudaFuncSetAttribute(tgemm<2, true>,  cudaFuncAttributeMaxDynamicSharedMemorySize, TG_SMEM);

    Ptrs p;
    cudaGetSymbolAddress((void**)&p.X, g_X);
    cudaGetSymbolAddress((void**)&p.Q, g_Q);
    cudaGetSymbolAddress((void**)&p.K, g_K);
    cudaGetSymbolAddress((void**)&p.Vt, g_Vt);
    cudaGetSymbolAddress((void**)&p.O, g_O);
    cudaGetSymbolAddress((void**)&p.P, g_P);
    cudaGetSymbolAddress((void**)&p.WqT, g_WqT);
    cudaGetSymbolAddress((void**)&p.WkT, g_WkT);
    cudaGetSymbolAddress((void**)&p.WvT, g_WvT);
    cudaGetSymbolAddress((void**)&p.WoT, g_WoT);
    cudaGetSymbolAddress((void**)&p.S, g_S);
    cudaGetSymbolAddress((void**)&p.H, g_H);
    cudaGetSymbolAddress((void**)&p.M1, g_M1);
    cudaGetSymbolAddress((void**)&p.S1, g_S1);
    cudaGetSymbolAddress((void**)&p.Qn, g_Qn);
    cudaGetSymbolAddress((void**)&p.Kp, g_Kp);
    cudaGetSymbolAddress((void**)&p.P1, g_P1);

    const int WG = Dn * Dn / 256;
    wcvt_t<<<WG, 256>>>(Wq, p.WqT);
    wcvt_t<<<WG, 256>>>(Wk, p.WkT);
    wcvt_t<<<WG, 256>>>(Wv, p.WvT);
    wcvt_t<<<WG, 256>>>(Wo, p.WoT);

    // ---- Stage A: backbone over input_h0 (n = 2050) ----
    build_x0h<<<dim3(NP * Dn / 256, Bn), 256>>>(seg0, p.X);
    run_backbone_tc(p, bq, bk, bv, bo, 2050, NP);
    copy_out<<<dim3(2016 * Dn / 256, Bn), 256>>>(p.H, out, 2016, NP, 0LL);
    copy_pad128<<<dim3(128 * Dn / 256), 256>>>(p.H, p.M1, NP, 2049);

    // ---- Stage B: summarize(seg1) (n = 514) ----
    build_xsh<<<dim3(NS * Dn / 256, Bn), 256>>>(seg1, pe, p.X);
    run_backbone_tc(p, bq, bk, bv, bo, 514, NS);
    copy_pad128<<<dim3(128 * Dn / 256), 256>>>(p.H, p.S1, NS, 512);

    // ---- Stage C: memory attention (tiny, fp32 path) ----
    dim3 gMem(Dn / 128, 1, 1);
    sgemm<false, true><<<gMem, 256>>>(p.S1, Wq_mem, p.Qn, bq_mem, Dn, Dn, 1.f);
    sgemm<false, true><<<gMem, 256>>>(p.M1, Wk_mem, p.Kp, bk_mem, Dn, Dn, 1.f);
    mem_attn<<<Bn, 256>>>(p.Qn, p.Kp, p.M1, p.P1);

    // ---- Stage D: backbone over input_h1 (n = 2082) ----
    build_x1h<<<dim3(NP * Dn / 256, Bn), 256>>>(seg0, seg1, p.P1, p.X);
    run_backbone_tc(p, bq, bk, bv, bo, 2082, NP);
    copy_out<<<dim3(2048 * Dn / 256, Bn), 256>>>(p.H, out, 2048, NP,
                                                 (long long)Bn * 2016 * Dn);
}